// round 9
// baseline (speedup 1.0000x reference)
#include <cuda_runtime.h>
#include <math.h>

typedef unsigned long long U64;
typedef long long i64;

namespace cfg {
constexpr int B = 256, T = 128, H = 512, L = 4, NT = 74;
constexpr int BH = B * H;
constexpr i64 BTH = (i64)B * T * H;
constexpr i64 O_X = 0;
constexpr i64 O_Y = O_X + BTH;
constexpr i64 O_N = O_Y + BTH;
constexpr i64 O_Q = O_N + BTH;
constexpr i64 O_K = O_Q + BTH;
constexpr i64 O_V = O_K + BTH;
constexpr i64 O_AO = O_V + BTH;
constexpr i64 O_S = O_AO + BTH;              // [B,T,T]
constexpr i64 O_LG = O_S + (i64)B * T * T;   // logits
constexpr i64 O_HB = O_LG + (i64)B * T * NT; // h ping-pong [2][L][BH]
constexpr i64 O_CB = O_HB + 2LL * L * BH;    // c [L][BH]
constexpr i64 O_NLL = O_CB + 2LL * L * BH;
constexpr i64 O_VLD = O_NLL + B * T;
constexpr i64 TOT = O_VLD + B * T;
}
__device__ float g_buf[cfg::TOT];

__device__ __forceinline__ U64 ffma2(U64 a, U64 b, U64 c) {
    U64 d; asm("fma.rn.f32x2 %0, %1, %2, %3;" : "=l"(d) : "l"(a), "l"(b), "l"(c));
    return d;
}
__device__ __forceinline__ U64 addf2(U64 a, U64 b) {
    U64 d; asm("add.rn.f32x2 %0, %1, %2;" : "=l"(d) : "l"(a), "l"(b));
    return d;
}
__device__ __forceinline__ float hsum2(U64 v) {
    float lo, hi; asm("mov.b64 {%0,%1}, %2;" : "=f"(lo), "=f"(hi) : "l"(v));
    return lo + hi;
}
__device__ __forceinline__ float sigf(float x) { return 1.f / (1.f + __expf(-x)); }

__device__ __forceinline__ float4 ldcg4(const float* p) {
    float4 v;
    asm volatile("ld.global.cg.v4.f32 {%0,%1,%2,%3}, [%4];"
                 : "=f"(v.x), "=f"(v.y), "=f"(v.z), "=f"(v.w) : "l"(p));
    return v;
}

__device__ __forceinline__ void cluster_bar() {
    asm volatile("barrier.cluster.arrive.aligned;" ::: "memory");
    asm volatile("barrier.cluster.wait.aligned;" ::: "memory");
}

// ---------------- cluster-persistent LSTM, split-k over 2 warp-groups --------
// 16 clusters x 8 CTAs. Cluster = 16 batch rows; CTA rank owns 64 h-cols
// (256 gate-cols). 256 threads = 2 warp-groups; wg0 does kp 0-3, wg1 kp 4-7
// of each staged 16-k chunk; f32x2 smem reduction per cell; wg0 epilogue.
__global__ void __launch_bounds__(256) __cluster_dims__(8, 1, 1) lstm_cluster(
    const float* __restrict__ x, float* __restrict__ y,
    float* __restrict__ hb, float* __restrict__ cbuf,
    const float* __restrict__ eWih, const float* __restrict__ eWhh,
    const float* __restrict__ ebih, const float* __restrict__ ebhh,
    const float* __restrict__ dWih, const float* __restrict__ dWhh,
    const float* __restrict__ dbih, const float* __restrict__ dbhh)
{
    using namespace cfg;
    constexpr int RS = 18;             // smem row stride (16 k + pad 2)
    constexpr int BUF = 272 * RS;      // 256 W rows + 16 A rows
    __shared__ float sm[2 * BUF];      // 39168 B, double-buffered
    const int tid = threadIdx.x;
    const int wg = tid >> 7;
    const int wtid = tid & 127;
    const int mg = wtid >> 5, ng = wtid & 31;
    const int rank = blockIdx.x & 7;
    const int r0 = (blockIdx.x >> 3) * 16;

    // zero own c slice and own h parity-1 slice (first 128 threads)
    if (wg == 0) {
#pragma unroll
        for (int l = 0; l < 4; ++l)
#pragma unroll
            for (int bb = 0; bb < 4; ++bb)
#pragma unroll
                for (int jj = 0; jj < 2; ++jj) {
                    i64 off = (i64)l * BH + (i64)(r0 + mg * 4 + bb) * H
                            + rank * 64 + ng + jj * 32;
                    cbuf[off] = 0.f;
                    hb[(i64)L * BH + off] = 0.f;
                }
    }
    __threadfence();
    cluster_bar();

    for (int tt = 0; tt < 2 * T; ++tt) {
        const int p = tt & 1;
        const bool enc = tt < T;
        const float* Wih = enc ? eWih : dWih;
        const float* Whh = enc ? eWhh : dWhh;
        const float* bih = enc ? ebih : dbih;
        const float* bhh = enc ? ebhh : dbhh;
        for (int l = 0; l < 4; ++l) {
            const float* xin;
            if (l)            xin = hb + (i64)p * L * BH + (i64)(l - 1) * BH;
            else if (enc)     xin = x + (i64)tt * BH;
            else if (tt == T) xin = hb + (i64)L * BH + 3LL * BH;
            else              xin = y + (i64)(tt - T - 1) * BH;
            const float* hp = hb + (i64)(1 - p) * L * BH + (i64)l * BH;
            float* ho = hb + (i64)p * L * BH + (i64)l * BH;
            float* yo = (!enc && l == 3) ? (y + (i64)(tt - T) * BH) : nullptr;
            const float* Wi = Wih + (i64)l * 2048 * 512;
            const float* Wh = Whh + (i64)l * 2048 * 512;

            U64 acc[4][8];
#pragma unroll
            for (int bb = 0; bb < 4; ++bb)
#pragma unroll
                for (int q = 0; q < 8; ++q) acc[bb][q] = 0ull;

            float4 pw[4], pa;
            // prefetch chunk 0 (256 threads x 4 float4 = 16KB W; 64 threads A)
#pragma unroll
            for (int i = 0; i < 4; ++i) {
                int lin = tid + i * 256, n = lin >> 2, c4 = (lin & 3) * 4;
                int wrow = ((n >> 6) << 9) + rank * 64 + (n & 63);
                pw[i] = *(const float4*)&Wi[(i64)wrow * 512 + c4];
            }
            if (tid < 64) {
                int row = tid >> 2, c4 = (tid & 3) * 4;
                pa = ldcg4(&xin[(i64)(r0 + row) * 512 + c4]);
            }

            for (int s = 0; s < 64; ++s) {
                float* buf = sm + (s & 1) * BUF;
#pragma unroll
                for (int i = 0; i < 4; ++i) {
                    int lin = tid + i * 256, n = lin >> 2, c4 = (lin & 3) * 4;
                    float* d = &buf[n * RS + c4];
                    d[0] = pw[i].x; d[1] = pw[i].y; d[2] = pw[i].z; d[3] = pw[i].w;
                }
                if (tid < 64) {
                    int row = tid >> 2, c4 = (tid & 3) * 4;
                    float* d = &buf[(256 + row) * RS + c4];
                    d[0] = pa.x; d[1] = pa.y; d[2] = pa.z; d[3] = pa.w;
                }
                __syncthreads();
                if (s < 63) {
                    const int sn = s + 1;
                    const float* A = (sn < 32) ? xin : hp;
                    const float* W = (sn < 32) ? Wi : Wh;
                    const int k0 = (sn & 31) * 16;
#pragma unroll
                    for (int i = 0; i < 4; ++i) {
                        int lin = tid + i * 256, n = lin >> 2, c4 = (lin & 3) * 4;
                        int wrow = ((n >> 6) << 9) + rank * 64 + (n & 63);
                        pw[i] = *(const float4*)&W[(i64)wrow * 512 + k0 + c4];
                    }
                    if (tid < 64) {
                        int row = tid >> 2, c4 = (tid & 3) * 4;
                        pa = ldcg4(&A[(i64)(r0 + row) * 512 + k0 + c4]);
                    }
                }
                const U64* wb = (const U64*)buf;
#pragma unroll
                for (int kk = 0; kk < 4; ++kk) {
                    const int kp = wg * 4 + kk;
                    U64 wv[8];
#pragma unroll
                    for (int g = 0; g < 4; ++g) {
                        wv[g * 2 + 0] = wb[(g * 64 + ng) * 9 + kp];
                        wv[g * 2 + 1] = wb[(g * 64 + 32 + ng) * 9 + kp];
                    }
#pragma unroll
                    for (int bb = 0; bb < 4; ++bb) {
                        U64 av = wb[(256 + mg * 4 + bb) * 9 + kp];
#pragma unroll
                        for (int q = 0; q < 8; ++q)
                            acc[bb][q] = ffma2(av, wv[q], acc[bb][q]);
                    }
                }
            }

            // split-k reduction: wg1 -> smem, wg0 adds (packed f32x2)
            __syncthreads();
            U64* red = (U64*)sm;
            if (wg == 1) {
#pragma unroll
                for (int bb = 0; bb < 4; ++bb)
#pragma unroll
                    for (int q = 0; q < 8; ++q)
                        red[(bb * 8 + q) * 128 + wtid] = acc[bb][q];
            }
            __syncthreads();
            if (wg == 0) {
                const float* bi = bih + (i64)l * 2048;
                const float* bh2 = bhh + (i64)l * 2048;
#pragma unroll
                for (int bb = 0; bb < 4; ++bb) {
                    const int b = r0 + mg * 4 + bb;
#pragma unroll
                    for (int q = 0; q < 8; ++q)
                        acc[bb][q] = addf2(acc[bb][q], red[(bb * 8 + q) * 128 + wtid]);
#pragma unroll
                    for (int jj = 0; jj < 2; ++jj) {
                        const int col = rank * 64 + ng + jj * 32;
                        float gi = hsum2(acc[bb][0 + jj]) + bi[col] + bh2[col];
                        float gf = hsum2(acc[bb][2 + jj]) + bi[512 + col] + bh2[512 + col];
                        float gg = hsum2(acc[bb][4 + jj]) + bi[1024 + col] + bh2[1024 + col];
                        float go = hsum2(acc[bb][6 + jj]) + bi[1536 + col] + bh2[1536 + col];
                        i64 ci = (i64)l * BH + (i64)b * H + col;
                        float cn = sigf(gf) * cbuf[ci] + sigf(gi) * tanhf(gg);
                        float hn = sigf(go) * tanhf(cn);
                        cbuf[ci] = cn;
                        ho[(i64)b * H + col] = hn;
                        if (yo) yo[(i64)b * H + col] = hn;
                    }
                }
            }
            __threadfence();
            cluster_bar();
        }
    }
}

// ---------------- generic GEMM: C = alpha*A@W^T + bias (transW optional) -----
__global__ void __launch_bounds__(128) gemm2_kernel(
    const float* __restrict__ A1, const float* __restrict__ W1,
    const float* __restrict__ bias, float* __restrict__ C,
    int M, int N, int K, int ldw, float alpha, int transW,
    i64 sA, i64 sW, i64 sC)
{
    __shared__ float a_s[64 * 34];
    __shared__ float w_s[64 * 34];
    const int tid = threadIdx.x;
    const int ng = tid & 15, mg = tid >> 4;
    const int m0 = blockIdx.x * 64, n0 = blockIdx.y * 64;
    const float* A = A1 + (i64)blockIdx.z * sA;
    const float* W = W1 + (i64)blockIdx.z * sW;
    float* Cb = C + (i64)blockIdx.z * sC;

    U64 acc[8][4];
#pragma unroll
    for (int mm = 0; mm < 8; ++mm)
#pragma unroll
        for (int nn = 0; nn < 4; ++nn) acc[mm][nn] = 0ull;

    for (int kc = 0; kc < K; kc += 32) {
        __syncthreads();
#pragma unroll
        for (int i = 0; i < 4; ++i) {
            int lin = tid + i * 128;
            int row = lin >> 3, c4 = (lin & 7) * 4;
            float4 v = *(const float4*)&A[(i64)(m0 + row) * K + kc + c4];
            float* d = &a_s[row * 34 + c4];
            d[0] = v.x; d[1] = v.y; d[2] = v.z; d[3] = v.w;
        }
        if (!transW) {
#pragma unroll
            for (int i = 0; i < 4; ++i) {
                int lin = tid + i * 128;
                int row = lin >> 3, c4 = (lin & 7) * 4;
                float4 v = make_float4(0.f, 0.f, 0.f, 0.f);
                if (n0 + row < N) v = *(const float4*)&W[(i64)(n0 + row) * ldw + kc + c4];
                float* d = &w_s[row * 34 + c4];
                d[0] = v.x; d[1] = v.y; d[2] = v.z; d[3] = v.w;
            }
        } else {
#pragma unroll
            for (int i = 0; i < 4; ++i) {
                int lin = tid + i * 128;
                int kk = lin >> 4, c4 = (lin & 15) * 4;
                float4 v = *(const float4*)&W[(i64)(kc + kk) * ldw + n0 + c4];
                w_s[(c4 + 0) * 34 + kk] = v.x;
                w_s[(c4 + 1) * 34 + kk] = v.y;
                w_s[(c4 + 2) * 34 + kk] = v.z;
                w_s[(c4 + 3) * 34 + kk] = v.w;
            }
        }
        __syncthreads();
#pragma unroll
        for (int kp = 0; kp < 16; ++kp) {
            U64 wv[4];
#pragma unroll
            for (int nn = 0; nn < 4; ++nn)
                wv[nn] = *(const U64*)&w_s[(ng + nn * 16) * 34 + kp * 2];
#pragma unroll
            for (int mm = 0; mm < 8; ++mm) {
                U64 av = *(const U64*)&a_s[(mg * 8 + mm) * 34 + kp * 2];
#pragma unroll
                for (int nn = 0; nn < 4; ++nn)
                    acc[mm][nn] = ffma2(av, wv[nn], acc[mm][nn]);
            }
        }
    }
#pragma unroll
    for (int mm = 0; mm < 8; ++mm) {
        const int m = m0 + mg * 8 + mm;
#pragma unroll
        for (int nn = 0; nn < 4; ++nn) {
            const int n = n0 + ng + nn * 16;
            if (n < N) {
                float v = hsum2(acc[mm][nn]) * alpha;
                if (bias) v += bias[n];
                Cb[(i64)m * N + n] = v;
            }
        }
    }
}

// ---------------- small kernels ----------------
__global__ void embed_kernel(const int* __restrict__ ids, const float* __restrict__ emb,
                             float* __restrict__ x) {
    int bid = blockIdx.x;              // b*T + t
    int b = bid >> 7, t = bid & 127;
    i64 id = ids[bid];
    const float4* s = (const float4*)(emb + id * cfg::H);
    float4* d = (float4*)(x + (i64)t * cfg::BH + (i64)b * cfg::H);
    d[threadIdx.x] = s[threadIdx.x];
}

__global__ void __launch_bounds__(128) ln_kernel(const float* __restrict__ y,
    const float* __restrict__ gam, const float* __restrict__ bet, float* __restrict__ out)
{
    using namespace cfg;
    int r = blockIdx.x;                 // t*B + b
    int t = r >> 8, bi = r & 255;
    int h = threadIdx.x * 4;
    float4 v = *(const float4*)&y[(i64)r * H + h];
    float s = v.x + v.y + v.z + v.w;
    float sq = v.x * v.x + v.y * v.y + v.z * v.z + v.w * v.w;
#pragma unroll
    for (int o = 16; o > 0; o >>= 1) {
        s += __shfl_xor_sync(0xffffffffu, s, o);
        sq += __shfl_xor_sync(0xffffffffu, sq, o);
    }
    __shared__ float ss[4], sqs[4];
    if ((threadIdx.x & 31) == 0) { ss[threadIdx.x >> 5] = s; sqs[threadIdx.x >> 5] = sq; }
    __syncthreads();
    s = ss[0] + ss[1] + ss[2] + ss[3];
    sq = sqs[0] + sqs[1] + sqs[2] + sqs[3];
    float mu = s * (1.f / 512.f);
    float rstd = rsqrtf(sq * (1.f / 512.f) - mu * mu + 1e-5f);
    float4 g4 = *(const float4*)&gam[h];
    float4 b4 = *(const float4*)&bet[h];
    float4 o;
    o.x = (v.x - mu) * rstd * g4.x + b4.x;
    o.y = (v.y - mu) * rstd * g4.y + b4.y;
    o.z = (v.z - mu) * rstd * g4.z + b4.z;
    o.w = (v.w - mu) * rstd * g4.w + b4.w;
    *(float4*)&out[(i64)bi * T * H + (i64)t * H + h] = o;
}

__global__ void softmax128_kernel(float* __restrict__ S) {
    float* row = S + (i64)blockIdx.x * 128;
    int tid = threadIdx.x;
    float v = row[tid];
    __shared__ float r1[4], r2[4];
    float m = v;
#pragma unroll
    for (int o = 16; o > 0; o >>= 1) m = fmaxf(m, __shfl_xor_sync(0xffffffffu, m, o));
    if ((tid & 31) == 0) r1[tid >> 5] = m;
    __syncthreads();
    m = fmaxf(fmaxf(r1[0], r1[1]), fmaxf(r1[2], r1[3]));
    float e = __expf(v - m), s = e;
#pragma unroll
    for (int o = 16; o > 0; o >>= 1) s += __shfl_xor_sync(0xffffffffu, s, o);
    if ((tid & 31) == 0) r2[tid >> 5] = s;
    __syncthreads();
    s = r2[0] + r2[1] + r2[2] + r2[3];
    row[tid] = e / s;
}

__global__ void tag_softmax_kernel(const float* __restrict__ logits,
    const int* __restrict__ tag_ids, float* __restrict__ prob,
    float* __restrict__ nll, float* __restrict__ valid)
{
    using namespace cfg;
    int r = blockIdx.x;
    int tid = threadIdx.x;
    const float* lr = logits + (i64)r * NT;
    float v = (tid < NT) ? lr[tid] : -1e30f;
    __shared__ float r1[4], r2[4];
    float m = v;
#pragma unroll
    for (int o = 16; o > 0; o >>= 1) m = fmaxf(m, __shfl_xor_sync(0xffffffffu, m, o));
    if ((tid & 31) == 0) r1[tid >> 5] = m;
    __syncthreads();
    m = fmaxf(fmaxf(r1[0], r1[1]), fmaxf(r1[2], r1[3]));
    float e = (tid < NT) ? __expf(v - m) : 0.f, s = e;
#pragma unroll
    for (int o = 16; o > 0; o >>= 1) s += __shfl_xor_sync(0xffffffffu, s, o);
    if ((tid & 31) == 0) r2[tid >> 5] = s;
    __syncthreads();
    s = r2[0] + r2[1] + r2[2] + r2[3];
    if (tid < NT) prob[(i64)r * NT + tid] = e / s;
    if (tid == 0) {
        int tg = tag_ids[r];
        float n = -(lr[tg] - m - __logf(s));
        float vl = (tg != 0) ? 1.f : 0.f;
        nll[r] = n * vl; valid[r] = vl;
    }
}

__global__ void loss_kernel(const float* __restrict__ nll, const float* __restrict__ valid,
                            float* __restrict__ out) {
    __shared__ float sn[256], sv[256];
    int tid = threadIdx.x;
    float a = 0.f, b = 0.f;
    for (int i = tid; i < cfg::B * cfg::T; i += 256) { a += nll[i]; b += valid[i]; }
    sn[tid] = a; sv[tid] = b;
    __syncthreads();
    for (int st = 128; st > 0; st >>= 1) {
        if (tid < st) { sn[tid] += sn[tid + st]; sv[tid] += sv[tid + st]; }
        __syncthreads();
    }
    if (tid == 0) out[0] = sn[0] / fmaxf(sv[0], 1.f);
}

// ---------------- host orchestration ----------------
extern "C" void kernel_launch(void* const* d_in, const int*, int, void* d_out, int) {
    using namespace cfg;
    const int* ids = (const int*)d_in[0];
    const int* tags = (const int*)d_in[1];
    const float* emb = (const float*)d_in[3];
    const float* eWih = (const float*)d_in[4];
    const float* eWhh = (const float*)d_in[5];
    const float* ebih = (const float*)d_in[6];
    const float* ebhh = (const float*)d_in[7];
    const float* dWih = (const float*)d_in[8];
    const float* dWhh = (const float*)d_in[9];
    const float* dbih = (const float*)d_in[10];
    const float* dbhh = (const float*)d_in[11];
    const float* ln_g = (const float*)d_in[12];
    const float* ln_b = (const float*)d_in[13];
    const float* Wq = (const float*)d_in[14];
    const float* bq = (const float*)d_in[15];
    const float* Wk = (const float*)d_in[16];
    const float* bk = (const float*)d_in[17];
    const float* Wv = (const float*)d_in[18];
    const float* bv = (const float*)d_in[19];
    const float* Wtag = (const float*)d_in[20];
    const float* btag = (const float*)d_in[21];

    float* buf = nullptr;
    cudaGetSymbolAddress((void**)&buf, g_buf);
    float* x = buf + O_X;  float* y = buf + O_Y;   float* nrm = buf + O_N;
    float* q = buf + O_Q;  float* kx = buf + O_K;  float* vx = buf + O_V;
    float* ao = buf + O_AO; float* sc = buf + O_S; float* lg = buf + O_LG;
    float* hb = buf + O_HB; float* cb = buf + O_CB;
    float* nllp = buf + O_NLL; float* vldp = buf + O_VLD;

    embed_kernel<<<B * T, 128>>>(ids, emb, x);
    lstm_cluster<<<128, 256>>>(x, y, hb, cb, eWih, eWhh, ebih, ebhh,
                               dWih, dWhh, dbih, dbhh);
    ln_kernel<<<T * B, 128>>>(y, ln_g, ln_b, nrm);

    const int Mq = B * T;  // 32768
    gemm2_kernel<<<dim3(Mq / 64, 8, 1), 128>>>(nrm, Wq, bq, q, Mq, 512, 512, 512,
                                               1.f, 0, 0, 0, 0);
    gemm2_kernel<<<dim3(Mq / 64, 8, 1), 128>>>(nrm, Wk, bk, kx, Mq, 512, 512, 512,
                                               1.f, 0, 0, 0, 0);
    gemm2_kernel<<<dim3(Mq / 64, 8, 1), 128>>>(nrm, Wv, bv, vx, Mq, 512, 512, 512,
                                               1.f, 0, 0, 0, 0);
    gemm2_kernel<<<dim3(2, 2, B), 128>>>(q, kx, nullptr, sc, 128, 128, 512, 512,
        0.044194173824159216f, 0, (i64)T * H, (i64)T * H, (i64)T * T);
    softmax128_kernel<<<B * T, 128>>>(sc);
    gemm2_kernel<<<dim3(2, 8, B), 128>>>(sc, vx, nullptr, ao, 128, 512, 128, 512,
        1.f, 1, (i64)T * T, (i64)T * H, (i64)T * H);
    gemm2_kernel<<<dim3(Mq / 64, 2, 1), 128>>>(ao, Wtag, btag, lg, Mq, NT, 512, 512,
                                               1.f, 0, 0, 0, 0);
    tag_softmax_kernel<<<B * T, 128>>>(lg, tags, (float*)d_out, nllp, vldp);
    loss_kernel<<<1, 256>>>(nllp, vldp, (float*)d_out + (i64)B * T * NT);
}

// round 10
// speedup vs baseline: 1.4023x; 1.4023x over previous
#include <cuda_runtime.h>
#include <math.h>

typedef unsigned long long U64;
typedef long long i64;

namespace cfg {
constexpr int B = 256, T = 128, H = 512, L = 4, NT = 74;
constexpr int BH = B * H;
constexpr i64 BTH = (i64)B * T * H;
constexpr i64 O_X = 0;
constexpr i64 O_Y = O_X + BTH;
constexpr i64 O_N = O_Y + BTH;
constexpr i64 O_Q = O_N + BTH;
constexpr i64 O_K = O_Q + BTH;
constexpr i64 O_V = O_K + BTH;
constexpr i64 O_AO = O_V + BTH;
constexpr i64 O_S = O_AO + BTH;              // [B,T,T]
constexpr i64 O_LG = O_S + (i64)B * T * T;   // logits
constexpr i64 O_HB = O_LG + (i64)B * T * NT; // h ping-pong [2][L][BH]
constexpr i64 O_CB = O_HB + 2LL * L * BH;    // c [L][BH]
constexpr i64 O_NLL = O_CB + 2LL * L * BH;
constexpr i64 O_VLD = O_NLL + B * T;
constexpr i64 TOT = O_VLD + B * T;
}
__device__ float g_buf[cfg::TOT];

__device__ __forceinline__ U64 ffma2(U64 a, U64 b, U64 c) {
    U64 d; asm("fma.rn.f32x2 %0, %1, %2, %3;" : "=l"(d) : "l"(a), "l"(b), "l"(c));
    return d;
}
__device__ __forceinline__ U64 addf2(U64 a, U64 b) {
    U64 d; asm("add.rn.f32x2 %0, %1, %2;" : "=l"(d) : "l"(a), "l"(b));
    return d;
}
__device__ __forceinline__ float hsum2(U64 v) {
    float lo, hi; asm("mov.b64 {%0,%1}, %2;" : "=f"(lo), "=f"(hi) : "l"(v));
    return lo + hi;
}
__device__ __forceinline__ float sigf(float x) { return 1.f / (1.f + __expf(-x)); }

__device__ __forceinline__ float4 ldcg4(const float* p) {
    float4 v;
    asm volatile("ld.global.cg.v4.f32 {%0,%1,%2,%3}, [%4];"
                 : "=f"(v.x), "=f"(v.y), "=f"(v.z), "=f"(v.w) : "l"(p));
    return v;
}

__device__ __forceinline__ void cluster_bar() {
    asm volatile("barrier.cluster.arrive.aligned;" ::: "memory");
    asm volatile("barrier.cluster.wait.aligned;" ::: "memory");
}

// ---------------- cluster-persistent LSTM, 32 independent clusters ----------
// 32 clusters x 8 CTAs x 128 threads (256 CTAs -> ~2 CTAs/SM for overlap).
// Cluster = 8 batch rows; CTA rank owns 64 h-cols (256 gate-rows of W).
// 4 warps: w&1 = batch-row half (4 rows), w>>1 = kp half (split-k).
// Per-thread acc[4 rows][8 gate-cols]; smem split-k reduction per cell.
__global__ void __launch_bounds__(128) __cluster_dims__(8, 1, 1) lstm_cluster(
    const float* __restrict__ x, float* __restrict__ y,
    float* __restrict__ hb, float* __restrict__ cbuf,
    const float* __restrict__ eWih, const float* __restrict__ eWhh,
    const float* __restrict__ ebih, const float* __restrict__ ebhh,
    const float* __restrict__ dWih, const float* __restrict__ dWhh,
    const float* __restrict__ dbih, const float* __restrict__ dbhh)
{
    using namespace cfg;
    constexpr int RS = 18;             // smem row stride (16 k + pad 2)
    constexpr int BUF = 264 * RS;      // 256 W rows + 8 A rows
    __shared__ float sm[2 * BUF];      // 38016 B double-buffered
    const int tid = threadIdx.x;
    const int lane = tid & 31;
    const int w = tid >> 5;
    const int rowg = w & 1;            // batch-row half
    const int kph = w >> 1;            // kp half
    const int rank = blockIdx.x & 7;
    const int r0 = (blockIdx.x >> 3) * 8;

    // zero own c slice and own h parity-1 slice (8 rows x 64 cols x 4 layers)
#pragma unroll
    for (int l = 0; l < 4; ++l)
        for (int e = tid; e < 8 * 64; e += 128) {
            int row = e >> 6, col = e & 63;
            i64 off = (i64)l * BH + (i64)(r0 + row) * H + rank * 64 + col;
            cbuf[off] = 0.f;
            hb[(i64)L * BH + off] = 0.f;
        }
    __threadfence();
    cluster_bar();

    for (int tt = 0; tt < 2 * T; ++tt) {
        const int p = tt & 1;
        const bool enc = tt < T;
        const float* Wih = enc ? eWih : dWih;
        const float* Whh = enc ? eWhh : dWhh;
        const float* bih = enc ? ebih : dbih;
        const float* bhh = enc ? ebhh : dbhh;
        for (int l = 0; l < 4; ++l) {
            const float* xin;
            if (l)            xin = hb + (i64)p * L * BH + (i64)(l - 1) * BH;
            else if (enc)     xin = x + (i64)tt * BH;
            else if (tt == T) xin = hb + (i64)L * BH + 3LL * BH;
            else              xin = y + (i64)(tt - T - 1) * BH;
            const float* hp = hb + (i64)(1 - p) * L * BH + (i64)l * BH;
            float* ho = hb + (i64)p * L * BH + (i64)l * BH;
            float* yo = (!enc && l == 3) ? (y + (i64)(tt - T) * BH) : nullptr;
            const float* Wi = Wih + (i64)l * 2048 * 512;
            const float* Wh = Whh + (i64)l * 2048 * 512;

            U64 acc[4][8];
#pragma unroll
            for (int bb = 0; bb < 4; ++bb)
#pragma unroll
                for (int q = 0; q < 8; ++q) acc[bb][q] = 0ull;

            float4 pw[8], pa;
            // prefetch chunk 0: W 16KB (128 thr x 8 f4), A 512B (32 thr x 1 f4)
#pragma unroll
            for (int i = 0; i < 8; ++i) {
                int lin = tid + i * 128, n = lin >> 2, c4 = (lin & 3) * 4;
                int wrow = ((n >> 6) << 9) + rank * 64 + (n & 63);
                pw[i] = *(const float4*)&Wi[(i64)wrow * 512 + c4];
            }
            if (tid < 32) {
                int row = tid >> 2, c4 = (tid & 3) * 4;
                pa = ldcg4(&xin[(i64)(r0 + row) * 512 + c4]);
            }

            for (int s = 0; s < 64; ++s) {
                float* buf = sm + (s & 1) * BUF;
#pragma unroll
                for (int i = 0; i < 8; ++i) {
                    int lin = tid + i * 128, n = lin >> 2, c4 = (lin & 3) * 4;
                    float* d = &buf[n * RS + c4];
                    d[0] = pw[i].x; d[1] = pw[i].y; d[2] = pw[i].z; d[3] = pw[i].w;
                }
                if (tid < 32) {
                    int row = tid >> 2, c4 = (tid & 3) * 4;
                    float* d = &buf[(256 + row) * RS + c4];
                    d[0] = pa.x; d[1] = pa.y; d[2] = pa.z; d[3] = pa.w;
                }
                __syncthreads();
                if (s < 63) {
                    const int sn = s + 1;
                    const float* A = (sn < 32) ? xin : hp;
                    const float* W = (sn < 32) ? Wi : Wh;
                    const int k0 = (sn & 31) * 16;
#pragma unroll
                    for (int i = 0; i < 8; ++i) {
                        int lin = tid + i * 128, n = lin >> 2, c4 = (lin & 3) * 4;
                        int wrow = ((n >> 6) << 9) + rank * 64 + (n & 63);
                        pw[i] = *(const float4*)&W[(i64)wrow * 512 + k0 + c4];
                    }
                    if (tid < 32) {
                        int row = tid >> 2, c4 = (tid & 3) * 4;
                        pa = ldcg4(&A[(i64)(r0 + row) * 512 + k0 + c4]);
                    }
                }
                const U64* wb = (const U64*)buf;
#pragma unroll
                for (int kk = 0; kk < 4; ++kk) {
                    const int kp = kph * 4 + kk;
                    U64 wv[8];
#pragma unroll
                    for (int g = 0; g < 4; ++g) {
                        wv[g * 2 + 0] = wb[(g * 64 + lane) * 9 + kp];
                        wv[g * 2 + 1] = wb[(g * 64 + 32 + lane) * 9 + kp];
                    }
#pragma unroll
                    for (int bb = 0; bb < 4; ++bb) {
                        U64 av = wb[(256 + rowg * 4 + bb) * 9 + kp];
#pragma unroll
                        for (int q = 0; q < 8; ++q)
                            acc[bb][q] = ffma2(av, wv[q], acc[bb][q]);
                    }
                }
            }

            // split-k reduction: kph=1 warps -> smem, kph=0 adds + epilogue
            __syncthreads();
            U64* red = (U64*)sm;
            if (kph == 1) {
#pragma unroll
                for (int bb = 0; bb < 4; ++bb)
#pragma unroll
                    for (int q = 0; q < 8; ++q)
                        red[((rowg * 4 + bb) * 8 + q) * 32 + lane] = acc[bb][q];
            }
            __syncthreads();
            if (kph == 0) {
                const float* bi = bih + (i64)l * 2048;
                const float* bh2 = bhh + (i64)l * 2048;
#pragma unroll
                for (int bb = 0; bb < 4; ++bb) {
                    const int b = r0 + rowg * 4 + bb;
#pragma unroll
                    for (int q = 0; q < 8; ++q)
                        acc[bb][q] = addf2(acc[bb][q],
                                           red[((rowg * 4 + bb) * 8 + q) * 32 + lane]);
#pragma unroll
                    for (int jj = 0; jj < 2; ++jj) {
                        const int col = rank * 64 + lane + jj * 32;
                        float gi = hsum2(acc[bb][0 + jj]) + bi[col] + bh2[col];
                        float gf = hsum2(acc[bb][2 + jj]) + bi[512 + col] + bh2[512 + col];
                        float gg = hsum2(acc[bb][4 + jj]) + bi[1024 + col] + bh2[1024 + col];
                        float go = hsum2(acc[bb][6 + jj]) + bi[1536 + col] + bh2[1536 + col];
                        i64 ci = (i64)l * BH + (i64)b * H + col;
                        float cn = sigf(gf) * cbuf[ci] + sigf(gi) * tanhf(gg);
                        float hn = sigf(go) * tanhf(cn);
                        cbuf[ci] = cn;
                        ho[(i64)b * H + col] = hn;
                        if (yo) yo[(i64)b * H + col] = hn;
                    }
                }
            }
            __threadfence();
            cluster_bar();
        }
    }
}

// ---------------- generic GEMM: C = alpha*A@W^T + bias (transW optional) -----
__global__ void __launch_bounds__(128) gemm2_kernel(
    const float* __restrict__ A1, const float* __restrict__ W1,
    const float* __restrict__ bias, float* __restrict__ C,
    int M, int N, int K, int ldw, float alpha, int transW,
    i64 sA, i64 sW, i64 sC)
{
    __shared__ float a_s[64 * 34];
    __shared__ float w_s[64 * 34];
    const int tid = threadIdx.x;
    const int ng = tid & 15, mg = tid >> 4;
    const int m0 = blockIdx.x * 64, n0 = blockIdx.y * 64;
    const float* A = A1 + (i64)blockIdx.z * sA;
    const float* W = W1 + (i64)blockIdx.z * sW;
    float* Cb = C + (i64)blockIdx.z * sC;

    U64 acc[8][4];
#pragma unroll
    for (int mm = 0; mm < 8; ++mm)
#pragma unroll
        for (int nn = 0; nn < 4; ++nn) acc[mm][nn] = 0ull;

    for (int kc = 0; kc < K; kc += 32) {
        __syncthreads();
#pragma unroll
        for (int i = 0; i < 4; ++i) {
            int lin = tid + i * 128;
            int row = lin >> 3, c4 = (lin & 7) * 4;
            float4 v = *(const float4*)&A[(i64)(m0 + row) * K + kc + c4];
            float* d = &a_s[row * 34 + c4];
            d[0] = v.x; d[1] = v.y; d[2] = v.z; d[3] = v.w;
        }
        if (!transW) {
#pragma unroll
            for (int i = 0; i < 4; ++i) {
                int lin = tid + i * 128;
                int row = lin >> 3, c4 = (lin & 7) * 4;
                float4 v = make_float4(0.f, 0.f, 0.f, 0.f);
                if (n0 + row < N) v = *(const float4*)&W[(i64)(n0 + row) * ldw + kc + c4];
                float* d = &w_s[row * 34 + c4];
                d[0] = v.x; d[1] = v.y; d[2] = v.z; d[3] = v.w;
            }
        } else {
#pragma unroll
            for (int i = 0; i < 4; ++i) {
                int lin = tid + i * 128;
                int kk = lin >> 4, c4 = (lin & 15) * 4;
                float4 v = *(const float4*)&W[(i64)(kc + kk) * ldw + n0 + c4];
                w_s[(c4 + 0) * 34 + kk] = v.x;
                w_s[(c4 + 1) * 34 + kk] = v.y;
                w_s[(c4 + 2) * 34 + kk] = v.z;
                w_s[(c4 + 3) * 34 + kk] = v.w;
            }
        }
        __syncthreads();
#pragma unroll
        for (int kp = 0; kp < 16; ++kp) {
            U64 wv[4];
#pragma unroll
            for (int nn = 0; nn < 4; ++nn)
                wv[nn] = *(const U64*)&w_s[(ng + nn * 16) * 34 + kp * 2];
#pragma unroll
            for (int mm = 0; mm < 8; ++mm) {
                U64 av = *(const U64*)&a_s[(mg * 8 + mm) * 34 + kp * 2];
#pragma unroll
                for (int nn = 0; nn < 4; ++nn)
                    acc[mm][nn] = ffma2(av, wv[nn], acc[mm][nn]);
            }
        }
    }
#pragma unroll
    for (int mm = 0; mm < 8; ++mm) {
        const int m = m0 + mg * 8 + mm;
#pragma unroll
        for (int nn = 0; nn < 4; ++nn) {
            const int n = n0 + ng + nn * 16;
            if (n < N) {
                float v = hsum2(acc[mm][nn]) * alpha;
                if (bias) v += bias[n];
                Cb[(i64)m * N + n] = v;
            }
        }
    }
}

// ---------------- small kernels ----------------
__global__ void embed_kernel(const int* __restrict__ ids, const float* __restrict__ emb,
                             float* __restrict__ x, int base) {
    int bid = base + blockIdx.x;       // b*T + t
    if (bid >= cfg::B * cfg::T) return;
    int b = bid >> 7, t = bid & 127;
    i64 id = ids[bid];
    const float4* s = (const float4*)(emb + id * cfg::H);
    float4* d = (float4*)(x + (i64)t * cfg::BH + (i64)b * cfg::H);
    d[threadIdx.x] = s[threadIdx.x];
}

__global__ void __launch_bounds__(128) ln_kernel(const float* __restrict__ y,
    const float* __restrict__ gam, const float* __restrict__ bet, float* __restrict__ out)
{
    using namespace cfg;
    int r = blockIdx.x;                 // t*B + b
    int t = r >> 8, bi = r & 255;
    int h = threadIdx.x * 4;
    float4 v = *(const float4*)&y[(i64)r * H + h];
    float s = v.x + v.y + v.z + v.w;
    float sq = v.x * v.x + v.y * v.y + v.z * v.z + v.w * v.w;
#pragma unroll
    for (int o = 16; o > 0; o >>= 1) {
        s += __shfl_xor_sync(0xffffffffu, s, o);
        sq += __shfl_xor_sync(0xffffffffu, sq, o);
    }
    __shared__ float ss[4], sqs[4];
    if ((threadIdx.x & 31) == 0) { ss[threadIdx.x >> 5] = s; sqs[threadIdx.x >> 5] = sq; }
    __syncthreads();
    s = ss[0] + ss[1] + ss[2] + ss[3];
    sq = sqs[0] + sqs[1] + sqs[2] + sqs[3];
    float mu = s * (1.f / 512.f);
    float rstd = rsqrtf(sq * (1.f / 512.f) - mu * mu + 1e-5f);
    float4 g4 = *(const float4*)&gam[h];
    float4 b4 = *(const float4*)&bet[h];
    float4 o;
    o.x = (v.x - mu) * rstd * g4.x + b4.x;
    o.y = (v.y - mu) * rstd * g4.y + b4.y;
    o.z = (v.z - mu) * rstd * g4.z + b4.z;
    o.w = (v.w - mu) * rstd * g4.w + b4.w;
    *(float4*)&out[(i64)bi * T * H + (i64)t * H + h] = o;
}

__global__ void softmax128_kernel(float* __restrict__ S) {
    float* row = S + (i64)blockIdx.x * 128;
    int tid = threadIdx.x;
    float v = row[tid];
    __shared__ float r1[4], r2[4];
    float m = v;
#pragma unroll
    for (int o = 16; o > 0; o >>= 1) m = fmaxf(m, __shfl_xor_sync(0xffffffffu, m, o));
    if ((tid & 31) == 0) r1[tid >> 5] = m;
    __syncthreads();
    m = fmaxf(fmaxf(r1[0], r1[1]), fmaxf(r1[2], r1[3]));
    float e = __expf(v - m), s = e;
#pragma unroll
    for (int o = 16; o > 0; o >>= 1) s += __shfl_xor_sync(0xffffffffu, s, o);
    if ((tid & 31) == 0) r2[tid >> 5] = s;
    __syncthreads();
    s = r2[0] + r2[1] + r2[2] + r2[3];
    row[tid] = e / s;
}

__global__ void tag_softmax_kernel(const float* __restrict__ logits,
    const int* __restrict__ tag_ids, float* __restrict__ prob,
    float* __restrict__ nll, float* __restrict__ valid)
{
    using namespace cfg;
    int r = blockIdx.x;
    int tid = threadIdx.x;
    const float* lr = logits + (i64)r * NT;
    float v = (tid < NT) ? lr[tid] : -1e30f;
    __shared__ float r1[4], r2[4];
    float m = v;
#pragma unroll
    for (int o = 16; o > 0; o >>= 1) m = fmaxf(m, __shfl_xor_sync(0xffffffffu, m, o));
    if ((tid & 31) == 0) r1[tid >> 5] = m;
    __syncthreads();
    m = fmaxf(fmaxf(r1[0], r1[1]), fmaxf(r1[2], r1[3]));
    float e = (tid < NT) ? __expf(v - m) : 0.f, s = e;
#pragma unroll
    for (int o = 16; o > 0; o >>= 1) s += __shfl_xor_sync(0xffffffffu, s, o);
    if ((tid & 31) == 0) r2[tid >> 5] = s;
    __syncthreads();
    s = r2[0] + r2[1] + r2[2] + r2[3];
    if (tid < NT) prob[(i64)r * NT + tid] = e / s;
    if (tid == 0) {
        int tg = tag_ids[r];
        float n = -(lr[tg] - m - __logf(s));
        float vl = (tg != 0) ? 1.f : 0.f;
        nll[r] = n * vl; valid[r] = vl;
    }
}

__global__ void loss_kernel(const float* __restrict__ nll, const float* __restrict__ valid,
                            float* __restrict__ out) {
    __shared__ float sn[256], sv[256];
    int tid = threadIdx.x;
    float a = 0.f, b = 0.f;
    for (int i = tid; i < cfg::B * cfg::T; i += 256) { a += nll[i]; b += valid[i]; }
    sn[tid] = a; sv[tid] = b;
    __syncthreads();
    for (int st = 128; st > 0; st >>= 1) {
        if (tid < st) { sn[tid] += sn[tid + st]; sv[tid] += sv[tid + st]; }
        __syncthreads();
    }
    if (tid == 0) out[0] = sn[0] / fmaxf(sv[0], 1.f);
}

// ---------------- host orchestration ----------------
extern "C" void kernel_launch(void* const* d_in, const int*, int, void* d_out, int) {
    using namespace cfg;
    const int* ids = (const int*)d_in[0];
    const int* tags = (const int*)d_in[1];
    const float* emb = (const float*)d_in[3];
    const float* eWih = (const float*)d_in[4];
    const float* eWhh = (const float*)d_in[5];
    const float* ebih = (const float*)d_in[6];
    const float* ebhh = (const float*)d_in[7];
    const float* dWih = (const float*)d_in[8];
    const float* dWhh = (const float*)d_in[9];
    const float* dbih = (const float*)d_in[10];
    const float* dbhh = (const float*)d_in[11];
    const float* ln_g = (const float*)d_in[12];
    const float* ln_b = (const float*)d_in[13];
    const float* Wq = (const float*)d_in[14];
    const float* bq = (const float*)d_in[15];
    const float* Wk = (const float*)d_in[16];
    const float* bk = (const float*)d_in[17];
    const float* Wv = (const float*)d_in[18];
    const float* bv = (const float*)d_in[19];
    const float* Wtag = (const float*)d_in[20];
    const float* btag = (const float*)d_in[21];

    float* buf = nullptr;
    cudaGetSymbolAddress((void**)&buf, g_buf);
    float* x = buf + O_X;  float* y = buf + O_Y;   float* nrm = buf + O_N;
    float* q = buf + O_Q;  float* kx = buf + O_K;  float* vx = buf + O_V;
    float* ao = buf + O_AO; float* sc = buf + O_S; float* lg = buf + O_LG;
    float* hb = buf + O_HB; float* cb = buf + O_CB;
    float* nllp = buf + O_NLL; float* vldp = buf + O_VLD;

    // embed in 5 slices so lstm_cluster is the 6th launch (ncu -s 5 -c 1)
    const int NB = B * T, SL = (NB + 4) / 5;   // 6554
    for (int i = 0; i < 5; ++i) {
        int base = i * SL;
        int cnt = (base + SL <= NB) ? SL : (NB - base);
        embed_kernel<<<cnt, 128>>>(ids, emb, x, base);
    }
    lstm_cluster<<<256, 128>>>(x, y, hb, cb, eWih, eWhh, ebih, ebhh,
                               dWih, dWhh, dbih, dbhh);
    ln_kernel<<<T * B, 128>>>(y, ln_g, ln_b, nrm);

    const int Mq = B * T;  // 32768
    gemm2_kernel<<<dim3(Mq / 64, 8, 1), 128>>>(nrm, Wq, bq, q, Mq, 512, 512, 512,
                                               1.f, 0, 0, 0, 0);
    gemm2_kernel<<<dim3(Mq / 64, 8, 1), 128>>>(nrm, Wk, bk, kx, Mq, 512, 512, 512,
                                               1.f, 0, 0, 0, 0);
    gemm2_kernel<<<dim3(Mq / 64, 8, 1), 128>>>(nrm, Wv, bv, vx, Mq, 512, 512, 512,
                                               1.f, 0, 0, 0, 0);
    gemm2_kernel<<<dim3(2, 2, B), 128>>>(q, kx, nullptr, sc, 128, 128, 512, 512,
        0.044194173824159216f, 0, (i64)T * H, (i64)T * H, (i64)T * T);
    softmax128_kernel<<<B * T, 128>>>(sc);
    gemm2_kernel<<<dim3(2, 8, B), 128>>>(sc, vx, nullptr, ao, 128, 512, 128, 512,
        1.f, 1, (i64)T * T, (i64)T * H, (i64)T * H);
    gemm2_kernel<<<dim3(Mq / 64, 2, 1), 128>>>(ao, Wtag, btag, lg, Mq, NT, 512, 512,
                                               1.f, 0, 0, 0, 0);
    tag_softmax_kernel<<<B * T, 128>>>(lg, tags, (float*)d_out, nllp, vldp);
    loss_kernel<<<1, 256>>>(nllp, vldp, (float*)d_out + (i64)B * T * NT);
}

// round 11
// speedup vs baseline: 1.4379x; 1.0253x over previous
#include <cuda_runtime.h>
#include <cuda_bf16.h>
#include <math.h>

typedef unsigned long long U64;
typedef unsigned int u32;
typedef long long i64;

namespace cfg {
constexpr int B = 256, T = 128, H = 512, L = 4, NT = 74;
constexpr int BH = B * H;
constexpr i64 BTH = (i64)B * T * H;
constexpr i64 O_Y = 0;
constexpr i64 O_N = O_Y + BTH;
constexpr i64 O_Q = O_N + BTH;
constexpr i64 O_K = O_Q + BTH;
constexpr i64 O_V = O_K + BTH;
constexpr i64 O_AO = O_V + BTH;
constexpr i64 O_S = O_AO + BTH;              // [B,T,T]
constexpr i64 O_LG = O_S + (i64)B * T * T;   // logits
constexpr i64 O_CB = O_LG + (i64)B * T * NT; // c state [L][BH]
constexpr i64 O_NLL = O_CB + (i64)L * BH;
constexpr i64 O_VLD = O_NLL + B * T;
constexpr i64 TOT = O_VLD + B * T;
}
__device__ float g_buf[cfg::TOT];
// W fragments: [sl 8][rank 8][kt 64][q 32][lane 32] x uint4 {bh0,bh1,bl0,bl1}
__device__ uint4 g_wf[8 * 8 * 64 * 32 * 32];
__device__ __nv_bfloat16 g_xh[cfg::BTH], g_xl[cfg::BTH];          // embedded x hi/lo
__device__ __nv_bfloat16 g_hh[2 * cfg::L * cfg::BH], g_hl[2 * cfg::L * cfg::BH];
__device__ __nv_bfloat16 g_yh[2 * cfg::BH], g_yl[2 * cfg::BH];    // decoder feedback

__device__ __forceinline__ U64 ffma2(U64 a, U64 b, U64 c) {
    U64 d; asm("fma.rn.f32x2 %0, %1, %2, %3;" : "=l"(d) : "l"(a), "l"(b), "l"(c));
    return d;
}
__device__ __forceinline__ float hsum2(U64 v) {
    float lo, hi; asm("mov.b64 {%0,%1}, %2;" : "=f"(lo), "=f"(hi) : "l"(v));
    return lo + hi;
}
__device__ __forceinline__ float sigf(float x) { return 1.f / (1.f + __expf(-x)); }

__device__ __forceinline__ u32 ldcg32(const __nv_bfloat16* p) {
    u32 v; asm volatile("ld.global.cg.u32 %0, [%1];" : "=r"(v) : "l"(p));
    return v;
}
__device__ __forceinline__ void mma16816(float* d, const u32* a, u32 b0, u32 b1) {
    asm volatile(
        "mma.sync.aligned.m16n8k16.row.col.f32.bf16.bf16.f32 "
        "{%0,%1,%2,%3}, {%4,%5,%6,%7}, {%8,%9}, {%0,%1,%2,%3};"
        : "+f"(d[0]), "+f"(d[1]), "+f"(d[2]), "+f"(d[3])
        : "r"(a[0]), "r"(a[1]), "r"(a[2]), "r"(a[3]), "r"(b0), "r"(b1));
}
__device__ __forceinline__ void cluster_bar() {
    asm volatile("barrier.cluster.arrive.aligned;" ::: "memory");
    asm volatile("barrier.cluster.wait.aligned;" ::: "memory");
}
__device__ __forceinline__ u32 bpack(float a, float b) {
    __nv_bfloat162 t(__float2bfloat16_rn(a), __float2bfloat16_rn(b));
    return *(u32*)&t;
}

// -------- W preconversion: fp32 [n][k] -> fragment-order bf16 hi/lo uint4 ----
// grid (kt 64, rank 8, sl 8), block (lane 32, q 32).
__global__ void wconv_kernel(
    const float* __restrict__ eWih, const float* __restrict__ eWhh,
    const float* __restrict__ dWih, const float* __restrict__ dWhh,
    uint4* __restrict__ wf)
{
    int lane = threadIdx.x, q = threadIdx.y;
    int kt = blockIdx.x, rank = blockIdx.y, sl = blockIdx.z;
    bool enc = sl < 4; int l = sl & 3;
    const float* Wih = (enc ? eWih : dWih) + (i64)l * 2048 * 512;
    const float* Whh = (enc ? eWhh : dWhh) + (i64)l * 2048 * 512;
    int n = (q & 3) * 512 + rank * 64 + (q >> 2) * 8 + (lane >> 2);
    int k0 = kt * 16 + (lane & 3) * 2;
    float v[4];
#pragma unroll
    for (int j = 0; j < 4; ++j) {
        int k = k0 + (j >> 1) * 8 + (j & 1);
        v[j] = (k < 512) ? Wih[(i64)n * 512 + k] : Whh[(i64)n * 512 + k - 512];
    }
    float hi[4], lo[4];
#pragma unroll
    for (int j = 0; j < 4; ++j) {
        __nv_bfloat16 h = __float2bfloat16_rn(v[j]);
        hi[j] = __bfloat162float(h);
        lo[j] = v[j] - hi[j];
    }
    uint4 o;
    o.x = bpack(hi[0], hi[1]); o.y = bpack(hi[2], hi[3]);
    o.z = bpack(lo[0], lo[1]); o.w = bpack(lo[2], lo[3]);
    wf[((((i64)sl * 8 + rank) * 64 + kt) * 32 + q) * 32 + lane] = o;
}

// -------- embedding gather + hi/lo split ----------
__global__ void embed_kernel(const int* __restrict__ ids, const float* __restrict__ emb,
                             __nv_bfloat16* __restrict__ xh, __nv_bfloat16* __restrict__ xl,
                             int base) {
    int bid = base + blockIdx.x;       // b*T + t
    if (bid >= cfg::B * cfg::T) return;
    int b = bid >> 7, t = bid & 127;
    i64 id = ids[bid];
    float4 v = ((const float4*)(emb + id * cfg::H))[threadIdx.x];
    i64 o = (i64)t * cfg::BH + (i64)b * cfg::H + threadIdx.x * 4;
    float vv[4] = {v.x, v.y, v.z, v.w};
#pragma unroll
    for (int j = 0; j < 4; ++j) {
        __nv_bfloat16 h = __float2bfloat16_rn(vv[j]);
        xh[o + j] = h;
        xl[o + j] = __float2bfloat16_rn(vv[j] - __bfloat162float(h));
    }
}

// -------- cluster-persistent LSTM on tensor cores (mma.sync bf16 3-term) -----
// 8 clusters x 8 CTAs x 128 thr. Cluster = 32 batch rows (2 M-tiles of 16);
// rank owns 64 h-cols; warp w owns n-quarter (jl tiles 2w,2w+1, all 4 gates).
__global__ void __launch_bounds__(128) __cluster_dims__(8, 1, 1) lstm_mma(
    float* __restrict__ y, float* __restrict__ cbuf,
    const __nv_bfloat16* __restrict__ xh, const __nv_bfloat16* __restrict__ xl,
    __nv_bfloat16* __restrict__ hh, __nv_bfloat16* __restrict__ hl,
    __nv_bfloat16* __restrict__ yh, __nv_bfloat16* __restrict__ yl,
    const uint4* __restrict__ wf,
    const float* __restrict__ ebih, const float* __restrict__ ebhh,
    const float* __restrict__ dbih, const float* __restrict__ dbhh)
{
    using namespace cfg;
    const int tid = threadIdx.x;
    const int lane = tid & 31, w = tid >> 5;
    const int gid = lane >> 2, tig = lane & 3;
    const int rank = blockIdx.x & 7;
    const int r0 = (blockIdx.x >> 3) * 32;

    // zero c and parity-1 h planes (own slice: 32 rows x 64 cols x 4 layers)
    for (int e = tid; e < 4 * 32 * 64; e += 128) {
        int l = e >> 11, row = (e >> 6) & 31, col = e & 63;
        i64 off = (i64)l * BH + (i64)(r0 + row) * H + rank * 64 + col;
        cbuf[off] = 0.f;
        hh[(i64)L * BH + off] = __nv_bfloat16(0.f);
        hl[(i64)L * BH + off] = __nv_bfloat16(0.f);
    }
    __threadfence();
    cluster_bar();

    const i64 rA0 = (i64)(r0 + gid) * H;          // mtile0 rows
    const i64 rA1 = (i64)(r0 + 16 + gid) * H;     // mtile1 rows

    for (int tt = 0; tt < 2 * T; ++tt) {
        const int p = tt & 1;
        const bool enc = tt < T;
        const float* bih = enc ? ebih : dbih;
        const float* bhh = enc ? ebhh : dbhh;
        for (int l = 0; l < 4; ++l) {
            const __nv_bfloat16 *axh, *axl;
            if (l)            { axh = hh + ((i64)p * L + l - 1) * BH; axl = hl + ((i64)p * L + l - 1) * BH; }
            else if (enc)     { axh = xh + (i64)tt * BH;             axl = xl + (i64)tt * BH; }
            else if (tt == T) { axh = hh + 7LL * BH;                 axl = hl + 7LL * BH; }
            else              { axh = yh + (i64)(1 - p) * BH;        axl = yl + (i64)(1 - p) * BH; }
            const __nv_bfloat16* hph = hh + ((i64)(1 - p) * L + l) * BH;
            const __nv_bfloat16* hpl = hl + ((i64)(1 - p) * L + l) * BH;
            const uint4* wfl = wf + (i64)((enc ? l : 4 + l) * 8 + rank) * 64 * 32 * 32;

            float acc[2][8][4];
#pragma unroll
            for (int m = 0; m < 2; ++m)
#pragma unroll
                for (int q = 0; q < 8; ++q)
#pragma unroll
                    for (int c = 0; c < 4; ++c) acc[m][q][c] = 0.f;

            // A fragment loader: [0..3] xh m0, [4..7] xh m1, [8..11] xl m0, [12..15] xl m1
            u32 cur[16], nxt[16];
            {
                int k0 = tig * 2;
                cur[0] = ldcg32(axh + rA0 + k0);      cur[1] = ldcg32(axh + rA0 + 8 * H + k0);
                cur[2] = ldcg32(axh + rA0 + k0 + 8);  cur[3] = ldcg32(axh + rA0 + 8 * H + k0 + 8);
                cur[4] = ldcg32(axh + rA1 + k0);      cur[5] = ldcg32(axh + rA1 + 8 * H + k0);
                cur[6] = ldcg32(axh + rA1 + k0 + 8);  cur[7] = ldcg32(axh + rA1 + 8 * H + k0 + 8);
                cur[8] = ldcg32(axl + rA0 + k0);      cur[9] = ldcg32(axl + rA0 + 8 * H + k0);
                cur[10] = ldcg32(axl + rA0 + k0 + 8); cur[11] = ldcg32(axl + rA0 + 8 * H + k0 + 8);
                cur[12] = ldcg32(axl + rA1 + k0);     cur[13] = ldcg32(axl + rA1 + 8 * H + k0);
                cur[14] = ldcg32(axl + rA1 + k0 + 8); cur[15] = ldcg32(axl + rA1 + 8 * H + k0 + 8);
            }
            for (int kt = 0; kt < 64; ++kt) {
                if (kt < 63) {
                    const int kn = kt + 1;
                    const __nv_bfloat16* sh = (kn < 32) ? axh : hph;
                    const __nv_bfloat16* sl2 = (kn < 32) ? axl : hpl;
                    int k0 = ((kn & 31) * 16) + tig * 2;
                    nxt[0] = ldcg32(sh + rA0 + k0);      nxt[1] = ldcg32(sh + rA0 + 8 * H + k0);
                    nxt[2] = ldcg32(sh + rA0 + k0 + 8);  nxt[3] = ldcg32(sh + rA0 + 8 * H + k0 + 8);
                    nxt[4] = ldcg32(sh + rA1 + k0);      nxt[5] = ldcg32(sh + rA1 + 8 * H + k0);
                    nxt[6] = ldcg32(sh + rA1 + k0 + 8);  nxt[7] = ldcg32(sh + rA1 + 8 * H + k0 + 8);
                    nxt[8] = ldcg32(sl2 + rA0 + k0);     nxt[9] = ldcg32(sl2 + rA0 + 8 * H + k0);
                    nxt[10] = ldcg32(sl2 + rA0 + k0 + 8); nxt[11] = ldcg32(sl2 + rA0 + 8 * H + k0 + 8);
                    nxt[12] = ldcg32(sl2 + rA1 + k0);    nxt[13] = ldcg32(sl2 + rA1 + 8 * H + k0);
                    nxt[14] = ldcg32(sl2 + rA1 + k0 + 8); nxt[15] = ldcg32(sl2 + rA1 + 8 * H + k0 + 8);
                }
                const uint4* wp = wfl + ((i64)kt * 32 + w * 8) * 32 + lane;
#pragma unroll
                for (int q = 0; q < 8; ++q) {
                    uint4 W4 = wp[q * 32];
                    mma16816(acc[0][q], cur + 0, W4.x, W4.y);   // xh*wh
                    mma16816(acc[1][q], cur + 4, W4.x, W4.y);
                    mma16816(acc[0][q], cur + 0, W4.z, W4.w);   // xh*wl
                    mma16816(acc[1][q], cur + 4, W4.z, W4.w);
                    mma16816(acc[0][q], cur + 8, W4.x, W4.y);   // xl*wh
                    mma16816(acc[1][q], cur + 12, W4.x, W4.y);
                }
                if (kt < 63) {
#pragma unroll
                    for (int i = 0; i < 16; ++i) cur[i] = nxt[i];
                }
            }

            // epilogue: thread owns 16 outputs (2 m x 2 rr x 2 jl x 2 cc)
            const float* bi = bih + (i64)l * 2048;
            const float* bh2 = bhh + (i64)l * 2048;
            float* yo = (!enc && l == 3) ? (y + (i64)(tt - T) * BH) : nullptr;
            const i64 hbase = ((i64)p * L + l) * BH;
#pragma unroll
            for (int m = 0; m < 2; ++m)
#pragma unroll
                for (int rr = 0; rr < 2; ++rr) {
                    const int row = r0 + m * 16 + gid + rr * 8;
#pragma unroll
                    for (int jj = 0; jj < 2; ++jj) {
                        const int colb = rank * 64 + (2 * w + jj) * 8 + tig * 2;
#pragma unroll
                        for (int cc = 0; cc < 2; ++cc) {
                            const int col = colb + cc;
                            const int ci = rr * 2 + cc;
                            float gi = acc[m][jj * 4 + 0][ci] + bi[col] + bh2[col];
                            float gf = acc[m][jj * 4 + 1][ci] + bi[512 + col] + bh2[512 + col];
                            float gg = acc[m][jj * 4 + 2][ci] + bi[1024 + col] + bh2[1024 + col];
                            float go = acc[m][jj * 4 + 3][ci] + bi[1536 + col] + bh2[1536 + col];
                            i64 cidx = (i64)l * BH + (i64)row * H + col;
                            float cn = sigf(gf) * cbuf[cidx] + sigf(gi) * tanhf(gg);
                            float hn = sigf(go) * tanhf(cn);
                            cbuf[cidx] = cn;
                            __nv_bfloat16 hb16 = __float2bfloat16_rn(hn);
                            __nv_bfloat16 lb16 = __float2bfloat16_rn(hn - __bfloat162float(hb16));
                            i64 hidx = hbase + (i64)row * H + col;
                            hh[hidx] = hb16;
                            hl[hidx] = lb16;
                            if (yo) {
                                yo[(i64)row * H + col] = hn;
                                yh[(i64)p * BH + (i64)row * H + col] = hb16;
                                yl[(i64)p * BH + (i64)row * H + col] = lb16;
                            }
                        }
                    }
                }
            __threadfence();
            cluster_bar();
        }
    }
}

// ---------------- generic GEMM: C = alpha*A@W^T + bias (transW optional) -----
__global__ void __launch_bounds__(128) gemm2_kernel(
    const float* __restrict__ A1, const float* __restrict__ W1,
    const float* __restrict__ bias, float* __restrict__ C,
    int M, int N, int K, int ldw, float alpha, int transW,
    i64 sA, i64 sW, i64 sC)
{
    __shared__ float a_s[64 * 34];
    __shared__ float w_s[64 * 34];
    const int tid = threadIdx.x;
    const int ng = tid & 15, mg = tid >> 4;
    const int m0 = blockIdx.x * 64, n0 = blockIdx.y * 64;
    const float* A = A1 + (i64)blockIdx.z * sA;
    const float* W = W1 + (i64)blockIdx.z * sW;
    float* Cb = C + (i64)blockIdx.z * sC;

    U64 acc[8][4];
#pragma unroll
    for (int mm = 0; mm < 8; ++mm)
#pragma unroll
        for (int nn = 0; nn < 4; ++nn) acc[mm][nn] = 0ull;

    for (int kc = 0; kc < K; kc += 32) {
        __syncthreads();
#pragma unroll
        for (int i = 0; i < 4; ++i) {
            int lin = tid + i * 128;
            int row = lin >> 3, c4 = (lin & 7) * 4;
            float4 v = *(const float4*)&A[(i64)(m0 + row) * K + kc + c4];
            float* d = &a_s[row * 34 + c4];
            d[0] = v.x; d[1] = v.y; d[2] = v.z; d[3] = v.w;
        }
        if (!transW) {
#pragma unroll
            for (int i = 0; i < 4; ++i) {
                int lin = tid + i * 128;
                int row = lin >> 3, c4 = (lin & 7) * 4;
                float4 v = make_float4(0.f, 0.f, 0.f, 0.f);
                if (n0 + row < N) v = *(const float4*)&W[(i64)(n0 + row) * ldw + kc + c4];
                float* d = &w_s[row * 34 + c4];
                d[0] = v.x; d[1] = v.y; d[2] = v.z; d[3] = v.w;
            }
        } else {
#pragma unroll
            for (int i = 0; i < 4; ++i) {
                int lin = tid + i * 128;
                int kk = lin >> 4, c4 = (lin & 15) * 4;
                float4 v = *(const float4*)&W[(i64)(kc + kk) * ldw + n0 + c4];
                w_s[(c4 + 0) * 34 + kk] = v.x;
                w_s[(c4 + 1) * 34 + kk] = v.y;
                w_s[(c4 + 2) * 34 + kk] = v.z;
                w_s[(c4 + 3) * 34 + kk] = v.w;
            }
        }
        __syncthreads();
#pragma unroll
        for (int kp = 0; kp < 16; ++kp) {
            U64 wv[4];
#pragma unroll
            for (int nn = 0; nn < 4; ++nn)
                wv[nn] = *(const U64*)&w_s[(ng + nn * 16) * 34 + kp * 2];
#pragma unroll
            for (int mm = 0; mm < 8; ++mm) {
                U64 av = *(const U64*)&a_s[(mg * 8 + mm) * 34 + kp * 2];
#pragma unroll
                for (int nn = 0; nn < 4; ++nn)
                    acc[mm][nn] = ffma2(av, wv[nn], acc[mm][nn]);
            }
        }
    }
#pragma unroll
    for (int mm = 0; mm < 8; ++mm) {
        const int m = m0 + mg * 8 + mm;
#pragma unroll
        for (int nn = 0; nn < 4; ++nn) {
            const int n = n0 + ng + nn * 16;
            if (n < N) {
                float v = hsum2(acc[mm][nn]) * alpha;
                if (bias) v += bias[n];
                Cb[(i64)m * N + n] = v;
            }
        }
    }
}

// ---------------- small kernels ----------------
__global__ void __launch_bounds__(128) ln_kernel(const float* __restrict__ y,
    const float* __restrict__ gam, const float* __restrict__ bet, float* __restrict__ out)
{
    using namespace cfg;
    int r = blockIdx.x;                 // t*B + b
    int t = r >> 8, bi = r & 255;
    int h = threadIdx.x * 4;
    float4 v = *(const float4*)&y[(i64)r * H + h];
    float s = v.x + v.y + v.z + v.w;
    float sq = v.x * v.x + v.y * v.y + v.z * v.z + v.w * v.w;
#pragma unroll
    for (int o = 16; o > 0; o >>= 1) {
        s += __shfl_xor_sync(0xffffffffu, s, o);
        sq += __shfl_xor_sync(0xffffffffu, sq, o);
    }
    __shared__ float ss[4], sqs[4];
    if ((threadIdx.x & 31) == 0) { ss[threadIdx.x >> 5] = s; sqs[threadIdx.x >> 5] = sq; }
    __syncthreads();
    s = ss[0] + ss[1] + ss[2] + ss[3];
    sq = sqs[0] + sqs[1] + sqs[2] + sqs[3];
    float mu = s * (1.f / 512.f);
    float rstd = rsqrtf(sq * (1.f / 512.f) - mu * mu + 1e-5f);
    float4 g4 = *(const float4*)&gam[h];
    float4 b4 = *(const float4*)&bet[h];
    float4 o;
    o.x = (v.x - mu) * rstd * g4.x + b4.x;
    o.y = (v.y - mu) * rstd * g4.y + b4.y;
    o.z = (v.z - mu) * rstd * g4.z + b4.z;
    o.w = (v.w - mu) * rstd * g4.w + b4.w;
    *(float4*)&out[(i64)bi * T * H + (i64)t * H + h] = o;
}

__global__ void softmax128_kernel(float* __restrict__ S) {
    float* row = S + (i64)blockIdx.x * 128;
    int tid = threadIdx.x;
    float v = row[tid];
    __shared__ float r1[4], r2[4];
    float m = v;
#pragma unroll
    for (int o = 16; o > 0; o >>= 1) m = fmaxf(m, __shfl_xor_sync(0xffffffffu, m, o));
    if ((tid & 31) == 0) r1[tid >> 5] = m;
    __syncthreads();
    m = fmaxf(fmaxf(r1[0], r1[1]), fmaxf(r1[2], r1[3]));
    float e = __expf(v - m), s = e;
#pragma unroll
    for (int o = 16; o > 0; o >>= 1) s += __shfl_xor_sync(0xffffffffu, s, o);
    if ((tid & 31) == 0) r2[tid >> 5] = s;
    __syncthreads();
    s = r2[0] + r2[1] + r2[2] + r2[3];
    row[tid] = e / s;
}

__global__ void tag_softmax_kernel(const float* __restrict__ logits,
    const int* __restrict__ tag_ids, float* __restrict__ prob,
    float* __restrict__ nll, float* __restrict__ valid)
{
    using namespace cfg;
    int r = blockIdx.x;
    int tid = threadIdx.x;
    const float* lr = logits + (i64)r * NT;
    float v = (tid < NT) ? lr[tid] : -1e30f;
    __shared__ float r1[4], r2[4];
    float m = v;
#pragma unroll
    for (int o = 16; o > 0; o >>= 1) m = fmaxf(m, __shfl_xor_sync(0xffffffffu, m, o));
    if ((tid & 31) == 0) r1[tid >> 5] = m;
    __syncthreads();
    m = fmaxf(fmaxf(r1[0], r1[1]), fmaxf(r1[2], r1[3]));
    float e = (tid < NT) ? __expf(v - m) : 0.f, s = e;
#pragma unroll
    for (int o = 16; o > 0; o >>= 1) s += __shfl_xor_sync(0xffffffffu, s, o);
    if ((tid & 31) == 0) r2[tid >> 5] = s;
    __syncthreads();
    s = r2[0] + r2[1] + r2[2] + r2[3];
    if (tid < NT) prob[(i64)r * NT + tid] = e / s;
    if (tid == 0) {
        int tg = tag_ids[r];
        float n = -(lr[tg] - m - __logf(s));
        float vl = (tg != 0) ? 1.f : 0.f;
        nll[r] = n * vl; valid[r] = vl;
    }
}

__global__ void loss_kernel(const float* __restrict__ nll, const float* __restrict__ valid,
                            float* __restrict__ out) {
    __shared__ float sn[256], sv[256];
    int tid = threadIdx.x;
    float a = 0.f, b = 0.f;
    for (int i = tid; i < cfg::B * cfg::T; i += 256) { a += nll[i]; b += valid[i]; }
    sn[tid] = a; sv[tid] = b;
    __syncthreads();
    for (int st = 128; st > 0; st >>= 1) {
        if (tid < st) { sn[tid] += sn[tid + st]; sv[tid] += sv[tid + st]; }
        __syncthreads();
    }
    if (tid == 0) out[0] = sn[0] / fmaxf(sv[0], 1.f);
}

// ---------------- host orchestration ----------------
extern "C" void kernel_launch(void* const* d_in, const int*, int, void* d_out, int) {
    using namespace cfg;
    const int* ids = (const int*)d_in[0];
    const int* tags = (const int*)d_in[1];
    const float* emb = (const float*)d_in[3];
    const float* eWih = (const float*)d_in[4];
    const float* eWhh = (const float*)d_in[5];
    const float* ebih = (const float*)d_in[6];
    const float* ebhh = (const float*)d_in[7];
    const float* dWih = (const float*)d_in[8];
    const float* dWhh = (const float*)d_in[9];
    const float* dbih = (const float*)d_in[10];
    const float* dbhh = (const float*)d_in[11];
    const float* ln_g = (const float*)d_in[12];
    const float* ln_b = (const float*)d_in[13];
    const float* Wq = (const float*)d_in[14];
    const float* bq = (const float*)d_in[15];
    const float* Wk = (const float*)d_in[16];
    const float* bk = (const float*)d_in[17];
    const float* Wv = (const float*)d_in[18];
    const float* bv = (const float*)d_in[19];
    const float* Wtag = (const float*)d_in[20];
    const float* btag = (const float*)d_in[21];

    float* buf = nullptr;
    cudaGetSymbolAddress((void**)&buf, g_buf);
    uint4* wf = nullptr;            cudaGetSymbolAddress((void**)&wf, g_wf);
    __nv_bfloat16 *xh, *xl, *hh, *hl, *yh, *yl;
    cudaGetSymbolAddress((void**)&xh, g_xh);
    cudaGetSymbolAddress((void**)&xl, g_xl);
    cudaGetSymbolAddress((void**)&hh, g_hh);
    cudaGetSymbolAddress((void**)&hl, g_hl);
    cudaGetSymbolAddress((void**)&yh, g_yh);
    cudaGetSymbolAddress((void**)&yl, g_yl);

    float* y = buf + O_Y;   float* nrm = buf + O_N;
    float* q = buf + O_Q;   float* kx = buf + O_K;  float* vx = buf + O_V;
    float* ao = buf + O_AO; float* sc = buf + O_S;  float* lg = buf + O_LG;
    float* cb = buf + O_CB;
    float* nllp = buf + O_NLL; float* vldp = buf + O_VLD;

    // launches 1-5: wconv + 4 embed slices (lstm_mma is #6 for ncu -s 5)
    wconv_kernel<<<dim3(64, 8, 8), dim3(32, 32)>>>(eWih, eWhh, dWih, dWhh, wf);
    for (int i = 0; i < 4; ++i)
        embed_kernel<<<8192, 128>>>(ids, emb, xh, xl, i * 8192);

    lstm_mma<<<64, 128>>>(y, cb, xh, xl, hh, hl, yh, yl, wf,
                          ebih, ebhh, dbih, dbhh);

    ln_kernel<<<T * B, 128>>>(y, ln_g, ln_b, nrm);

    const int Mq = B * T;  // 32768
    gemm2_kernel<<<dim3(Mq / 64, 8, 1), 128>>>(nrm, Wq, bq, q, Mq, 512, 512, 512,
                                               1.f, 0, 0, 0, 0);
    gemm2_kernel<<<dim3(Mq / 64, 8, 1), 128>>>(nrm, Wk, bk, kx, Mq, 512, 512, 512,
                                               1.f, 0, 0, 0, 0);
    gemm2_kernel<<<dim3(Mq / 64, 8, 1), 128>>>(nrm, Wv, bv, vx, Mq, 512, 512, 512,
                                               1.f, 0, 0, 0, 0);
    gemm2_kernel<<<dim3(2, 2, B), 128>>>(q, kx, nullptr, sc, 128, 128, 512, 512,
        0.044194173824159216f, 0, (i64)T * H, (i64)T * H, (i64)T * T);
    softmax128_kernel<<<B * T, 128>>>(sc);
    gemm2_kernel<<<dim3(2, 8, B), 128>>>(sc, vx, nullptr, ao, 128, 512, 128, 512,
        1.f, 1, (i64)T * T, (i64)T * H, (i64)T * H);
    gemm2_kernel<<<dim3(Mq / 64, 2, 1), 128>>>(ao, Wtag, btag, lg, Mq, NT, 512, 512,
                                               1.f, 0, 0, 0, 0);
    tag_softmax_kernel<<<B * T, 128>>>(lg, tags, (float*)d_out, nllp, vldp);
    loss_kernel<<<1, 256>>>(nllp, vldp, (float*)d_out + (i64)B * T * NT);
}

// round 13
// speedup vs baseline: 1.7922x; 1.2464x over previous
#include <cuda_runtime.h>
#include <cuda_bf16.h>
#include <math.h>

typedef unsigned long long U64;
typedef unsigned int u32;
typedef long long i64;

namespace cfg {
constexpr int B = 256, T = 128, H = 512, L = 4, NT = 74;
constexpr int BH = B * H;
constexpr i64 BTH = (i64)B * T * H;
constexpr i64 O_Y = 0;
constexpr i64 O_N = O_Y + BTH;
constexpr i64 O_Q = O_N + BTH;
constexpr i64 O_K = O_Q + BTH;
constexpr i64 O_V = O_K + BTH;
constexpr i64 O_AO = O_V + BTH;
constexpr i64 O_S = O_AO + BTH;              // [B,T,T]
constexpr i64 O_LG = O_S + (i64)B * T * T;   // logits
constexpr i64 O_CB = O_LG + (i64)B * T * NT; // c state [L][BH]
constexpr i64 O_NLL = O_CB + (i64)L * BH;
constexpr i64 O_VLD = O_NLL + B * T;
constexpr i64 TOT = O_VLD + B * T;
}
__device__ float g_buf[cfg::TOT];
// W fragments: [sl 8][rank 8][kt 64][q 32][lane 32] x uint4 {bh0,bh1,bl0,bl1}
__device__ uint4 g_wf[8 * 8 * 64 * 32 * 32];
__device__ __nv_bfloat16 g_xh[cfg::BTH], g_xl[cfg::BTH];
__device__ __nv_bfloat16 g_hh[2 * cfg::L * cfg::BH], g_hl[2 * cfg::L * cfg::BH];
__device__ __nv_bfloat16 g_yh[2 * cfg::BH], g_yl[2 * cfg::BH];

__device__ __forceinline__ U64 ffma2(U64 a, U64 b, U64 c) {
    U64 d; asm("fma.rn.f32x2 %0, %1, %2, %3;" : "=l"(d) : "l"(a), "l"(b), "l"(c));
    return d;
}
__device__ __forceinline__ float hsum2(U64 v) {
    float lo, hi; asm("mov.b64 {%0,%1}, %2;" : "=f"(lo), "=f"(hi) : "l"(v));
    return lo + hi;
}
__device__ __forceinline__ float sigf(float x) { return 1.f / (1.f + __expf(-x)); }

__device__ __forceinline__ u32 ldcg32(const __nv_bfloat16* p) {
    u32 v; asm volatile("ld.global.cg.u32 %0, [%1];" : "=r"(v) : "l"(p));
    return v;
}
__device__ __forceinline__ void mma16816(float* d, const u32* a, u32 b0, u32 b1) {
    asm volatile(
        "mma.sync.aligned.m16n8k16.row.col.f32.bf16.bf16.f32 "
        "{%0,%1,%2,%3}, {%4,%5,%6,%7}, {%8,%9}, {%0,%1,%2,%3};"
        : "+f"(d[0]), "+f"(d[1]), "+f"(d[2]), "+f"(d[3])
        : "r"(a[0]), "r"(a[1]), "r"(a[2]), "r"(a[3]), "r"(b0), "r"(b1));
}
__device__ __forceinline__ void cluster_bar() {
    asm volatile("barrier.cluster.arrive.aligned;" ::: "memory");
    asm volatile("barrier.cluster.wait.aligned;" ::: "memory");
}
__device__ __forceinline__ u32 bpack(float a, float b) {
    __nv_bfloat162 t(__float2bfloat16_rn(a), __float2bfloat16_rn(b));
    return *(u32*)&t;
}

// -------- W preconversion (R11-validated layout) ----------
// grid (kt 64, rank 8, sl 8), block (lane 32, q 32).
__global__ void wconv_kernel(
    const float* __restrict__ eWih, const float* __restrict__ eWhh,
    const float* __restrict__ dWih, const float* __restrict__ dWhh,
    uint4* __restrict__ wf)
{
    int lane = threadIdx.x, q = threadIdx.y;
    int kt = blockIdx.x, rank = blockIdx.y, sl = blockIdx.z;
    bool enc = sl < 4; int l = sl & 3;
    const float* Wih = (enc ? eWih : dWih) + (i64)l * 2048 * 512;
    const float* Whh = (enc ? eWhh : dWhh) + (i64)l * 2048 * 512;
    int n = (q & 3) * 512 + rank * 64 + (q >> 2) * 8 + (lane >> 2);
    int k0 = kt * 16 + (lane & 3) * 2;
    float v[4];
#pragma unroll
    for (int j = 0; j < 4; ++j) {
        int k = k0 + (j >> 1) * 8 + (j & 1);
        v[j] = (k < 512) ? Wih[(i64)n * 512 + k] : Whh[(i64)n * 512 + k - 512];
    }
    float hi[4], lo[4];
#pragma unroll
    for (int j = 0; j < 4; ++j) {
        __nv_bfloat16 h = __float2bfloat16_rn(v[j]);
        hi[j] = __bfloat162float(h);
        lo[j] = v[j] - hi[j];
    }
    uint4 o;
    o.x = bpack(hi[0], hi[1]); o.y = bpack(hi[2], hi[3]);
    o.z = bpack(lo[0], lo[1]); o.w = bpack(lo[2], lo[3]);
    wf[((((i64)sl * 8 + rank) * 64 + kt) * 32 + q) * 32 + lane] = o;
}

// -------- embedding gather + hi/lo split ----------
__global__ void embed_kernel(const int* __restrict__ ids, const float* __restrict__ emb,
                             __nv_bfloat16* __restrict__ xh, __nv_bfloat16* __restrict__ xl,
                             int base) {
    int bid = base + blockIdx.x;
    if (bid >= cfg::B * cfg::T) return;
    int b = bid >> 7, t = bid & 127;
    i64 id = ids[bid];
    float4 v = ((const float4*)(emb + id * cfg::H))[threadIdx.x];
    i64 o = (i64)t * cfg::BH + (i64)b * cfg::H + threadIdx.x * 4;
    float vv[4] = {v.x, v.y, v.z, v.w};
#pragma unroll
    for (int j = 0; j < 4; ++j) {
        __nv_bfloat16 h = __float2bfloat16_rn(vv[j]);
        xh[o + j] = h;
        xl[o + j] = __float2bfloat16_rn(vv[j] - __bfloat162float(h));
    }
}

// -------- cluster-persistent LSTM on mma.sync, 16 clusters x 8 CTAs ---------
// 128 CTAs x 256 threads (8 warps = 2/SMSP). Cluster = 16 batch rows (M=16);
// rank owns 64 h-cols; warp w owns jl-tile w (8 cols) x 4 gates (q = 4w+g).
__global__ void __launch_bounds__(256) __cluster_dims__(8, 1, 1) lstm_mma(
    float* __restrict__ y, float* __restrict__ cbuf,
    const __nv_bfloat16* __restrict__ xh, const __nv_bfloat16* __restrict__ xl,
    __nv_bfloat16* __restrict__ hh, __nv_bfloat16* __restrict__ hl,
    __nv_bfloat16* __restrict__ yh, __nv_bfloat16* __restrict__ yl,
    const uint4* __restrict__ wf,
    const float* __restrict__ ebih, const float* __restrict__ ebhh,
    const float* __restrict__ dbih, const float* __restrict__ dbhh)
{
    using namespace cfg;
    const int tid = threadIdx.x;
    const int lane = tid & 31, w = tid >> 5;
    const int gid = lane >> 2, tig = lane & 3;
    const int rank = blockIdx.x & 7;
    const int r0 = (blockIdx.x >> 3) * 16;

    // zero c and parity-1 h planes (own slice: 16 rows x 64 cols x 4 layers)
    for (int e = tid; e < 4 * 16 * 64; e += 256) {
        int l = e >> 10, row = (e >> 6) & 15, col = e & 63;
        i64 off = (i64)l * BH + (i64)(r0 + row) * H + rank * 64 + col;
        cbuf[off] = 0.f;
        hh[(i64)L * BH + off] = __nv_bfloat16(0.f);
        hl[(i64)L * BH + off] = __nv_bfloat16(0.f);
    }
    __threadfence();
    cluster_bar();

    const i64 rA = (i64)(r0 + gid) * H;

    for (int tt = 0; tt < 2 * T; ++tt) {
        const int p = tt & 1;
        const bool enc = tt < T;
        const float* bih = enc ? ebih : dbih;
        const float* bhh = enc ? ebhh : dbhh;
        for (int l = 0; l < 4; ++l) {
            const __nv_bfloat16 *axh, *axl;
            if (l)            { axh = hh + ((i64)p * L + l - 1) * BH; axl = hl + ((i64)p * L + l - 1) * BH; }
            else if (enc)     { axh = xh + (i64)tt * BH;             axl = xl + (i64)tt * BH; }
            else if (tt == T) { axh = hh + 7LL * BH;                 axl = hl + 7LL * BH; }
            else              { axh = yh + (i64)(1 - p) * BH;        axl = yl + (i64)(1 - p) * BH; }
            const __nv_bfloat16* hph = hh + ((i64)(1 - p) * L + l) * BH;
            const __nv_bfloat16* hpl = hl + ((i64)(1 - p) * L + l) * BH;
            const uint4* wfl = wf + (i64)((enc ? l : 4 + l) * 8 + rank) * 64 * 32 * 32;

            float acc[4][4];
#pragma unroll
            for (int g = 0; g < 4; ++g)
#pragma unroll
                for (int c = 0; c < 4; ++c) acc[g][c] = 0.f;

            // A fragments: [0..3] hi, [4..7] lo (single M=16 tile)
            u32 cur[8], nxt[8];
            {
                int k0 = tig * 2;
                cur[0] = ldcg32(axh + rA + k0);     cur[1] = ldcg32(axh + rA + 8 * H + k0);
                cur[2] = ldcg32(axh + rA + k0 + 8); cur[3] = ldcg32(axh + rA + 8 * H + k0 + 8);
                cur[4] = ldcg32(axl + rA + k0);     cur[5] = ldcg32(axl + rA + 8 * H + k0);
                cur[6] = ldcg32(axl + rA + k0 + 8); cur[7] = ldcg32(axl + rA + 8 * H + k0 + 8);
            }
            for (int kt = 0; kt < 64; ++kt) {
                if (kt < 63) {
                    const int kn = kt + 1;
                    const __nv_bfloat16* sh = (kn < 32) ? axh : hph;
                    const __nv_bfloat16* sl2 = (kn < 32) ? axl : hpl;
                    int k0 = ((kn & 31) * 16) + tig * 2;
                    nxt[0] = ldcg32(sh + rA + k0);      nxt[1] = ldcg32(sh + rA + 8 * H + k0);
                    nxt[2] = ldcg32(sh + rA + k0 + 8);  nxt[3] = ldcg32(sh + rA + 8 * H + k0 + 8);
                    nxt[4] = ldcg32(sl2 + rA + k0);     nxt[5] = ldcg32(sl2 + rA + 8 * H + k0);
                    nxt[6] = ldcg32(sl2 + rA + k0 + 8); nxt[7] = ldcg32(sl2 + rA + 8 * H + k0 + 8);
                }
                const uint4* wp = wfl + ((i64)kt * 32 + w * 4) * 32 + lane;
#pragma unroll
                for (int g = 0; g < 4; ++g) {
                    uint4 W4 = wp[g * 32];
                    mma16816(acc[g], cur + 0, W4.x, W4.y);   // ah*wh
                    mma16816(acc[g], cur + 0, W4.z, W4.w);   // ah*wl
                    mma16816(acc[g], cur + 4, W4.x, W4.y);   // al*wh
                }
                if (kt < 63) {
#pragma unroll
                    for (int i = 0; i < 8; ++i) cur[i] = nxt[i];
                }
            }

            // epilogue: thread owns 4 outputs (2 rr x 2 cc), col tile = w
            const float* bi = bih + (i64)l * 2048;
            const float* bh2 = bhh + (i64)l * 2048;
            float* yo = (!enc && l == 3) ? (y + (i64)(tt - T) * BH) : nullptr;
            const i64 hbase = ((i64)p * L + l) * BH;
#pragma unroll
            for (int rr = 0; rr < 2; ++rr) {
                const int row = r0 + gid + rr * 8;
#pragma unroll
                for (int cc = 0; cc < 2; ++cc) {
                    const int col = rank * 64 + w * 8 + tig * 2 + cc;
                    const int ci = rr * 2 + cc;
                    float gi = acc[0][ci] + bi[col] + bh2[col];
                    float gf = acc[1][ci] + bi[512 + col] + bh2[512 + col];
                    float gg = acc[2][ci] + bi[1024 + col] + bh2[1024 + col];
                    float go = acc[3][ci] + bi[1536 + col] + bh2[1536 + col];
                    i64 cidx = (i64)l * BH + (i64)row * H + col;
                    float cn = sigf(gf) * cbuf[cidx] + sigf(gi) * tanhf(gg);
                    float hn = sigf(go) * tanhf(cn);
                    cbuf[cidx] = cn;
                    __nv_bfloat16 hb16 = __float2bfloat16_rn(hn);
                    __nv_bfloat16 lb16 = __float2bfloat16_rn(hn - __bfloat162float(hb16));
                    i64 hidx = hbase + (i64)row * H + col;
                    hh[hidx] = hb16;
                    hl[hidx] = lb16;
                    if (yo) {
                        yo[(i64)row * H + col] = hn;
                        yh[(i64)p * BH + (i64)row * H + col] = hb16;
                        yl[(i64)p * BH + (i64)row * H + col] = lb16;
                    }
                }
            }
            __threadfence();
            cluster_bar();
        }
    }
}

// ---------------- generic GEMM (R8-validated) ----------------
__global__ void __launch_bounds__(128) gemm2_kernel(
    const float* __restrict__ A1, const float* __restrict__ W1,
    const float* __restrict__ bias, float* __restrict__ C,
    int M, int N, int K, int ldw, float alpha, int transW,
    i64 sA, i64 sW, i64 sC)
{
    __shared__ float a_s[64 * 34];
    __shared__ float w_s[64 * 34];
    const int tid = threadIdx.x;
    const int ng = tid & 15, mg = tid >> 4;
    const int m0 = blockIdx.x * 64, n0 = blockIdx.y * 64;
    const float* A = A1 + (i64)blockIdx.z * sA;
    const float* W = W1 + (i64)blockIdx.z * sW;
    float* Cb = C + (i64)blockIdx.z * sC;
    U64 acc[8][4];
#pragma unroll
    for (int mm = 0; mm < 8; ++mm)
#pragma unroll
        for (int nn = 0; nn < 4; ++nn) acc[mm][nn] = 0ull;
    for (int kc = 0; kc < K; kc += 32) {
        __syncthreads();
#pragma unroll
        for (int i = 0; i < 4; ++i) {
            int lin = tid + i * 128;
            int row = lin >> 3, c4 = (lin & 7) * 4;
            float4 v = *(const float4*)&A[(i64)(m0 + row) * K + kc + c4];
            float* d = &a_s[row * 34 + c4];
            d[0] = v.x; d[1] = v.y; d[2] = v.z; d[3] = v.w;
        }
        if (!transW) {
#pragma unroll
            for (int i = 0; i < 4; ++i) {
                int lin = tid + i * 128;
                int row = lin >> 3, c4 = (lin & 7) * 4;
                float4 v = make_float4(0.f, 0.f, 0.f, 0.f);
                if (n0 + row < N) v = *(const float4*)&W[(i64)(n0 + row) * ldw + kc + c4];
                float* d = &w_s[row * 34 + c4];
                d[0] = v.x; d[1] = v.y; d[2] = v.z; d[3] = v.w;
            }
        } else {
#pragma unroll
            for (int i = 0; i < 4; ++i) {
                int lin = tid + i * 128;
                int kk = lin >> 4, c4 = (lin & 15) * 4;
                float4 v = *(const float4*)&W[(i64)(kc + kk) * ldw + n0 + c4];
                w_s[(c4 + 0) * 34 + kk] = v.x;
                w_s[(c4 + 1) * 34 + kk] = v.y;
                w_s[(c4 + 2) * 34 + kk] = v.z;
                w_s[(c4 + 3) * 34 + kk] = v.w;
            }
        }
        __syncthreads();
#pragma unroll
        for (int kp = 0; kp < 16; ++kp) {
            U64 wv[4];
#pragma unroll
            for (int nn = 0; nn < 4; ++nn)
                wv[nn] = *(const U64*)&w_s[(ng + nn * 16) * 34 + kp * 2];
#pragma unroll
            for (int mm = 0; mm < 8; ++mm) {
                U64 av = *(const U64*)&a_s[(mg * 8 + mm) * 34 + kp * 2];
#pragma unroll
                for (int nn = 0; nn < 4; ++nn)
                    acc[mm][nn] = ffma2(av, wv[nn], acc[mm][nn]);
            }
        }
    }
#pragma unroll
    for (int mm = 0; mm < 8; ++mm) {
        const int m = m0 + mg * 8 + mm;
#pragma unroll
        for (int nn = 0; nn < 4; ++nn) {
            const int n = n0 + ng + nn * 16;
            if (n < N) {
                float v = hsum2(acc[mm][nn]) * alpha;
                if (bias) v += bias[n];
                Cb[(i64)m * N + n] = v;
            }
        }
    }
}

// ---------------- small kernels ----------------
__global__ void __launch_bounds__(128) ln_kernel(const float* __restrict__ y,
    const float* __restrict__ gam, const float* __restrict__ bet, float* __restrict__ out)
{
    using namespace cfg;
    int r = blockIdx.x;
    int t = r >> 8, bi = r & 255;
    int h = threadIdx.x * 4;
    float4 v = *(const float4*)&y[(i64)r * H + h];
    float s = v.x + v.y + v.z + v.w;
    float sq = v.x * v.x + v.y * v.y + v.z * v.z + v.w * v.w;
#pragma unroll
    for (int o = 16; o > 0; o >>= 1) {
        s += __shfl_xor_sync(0xffffffffu, s, o);
        sq += __shfl_xor_sync(0xffffffffu, sq, o);
    }
    __shared__ float ss[4], sqs[4];
    if ((threadIdx.x & 31) == 0) { ss[threadIdx.x >> 5] = s; sqs[threadIdx.x >> 5] = sq; }
    __syncthreads();
    s = ss[0] + ss[1] + ss[2] + ss[3];
    sq = sqs[0] + sqs[1] + sqs[2] + sqs[3];
    float mu = s * (1.f / 512.f);
    float rstd = rsqrtf(sq * (1.f / 512.f) - mu * mu + 1e-5f);
    float4 g4 = *(const float4*)&gam[h];
    float4 b4 = *(const float4*)&bet[h];
    float4 o;
    o.x = (v.x - mu) * rstd * g4.x + b4.x;
    o.y = (v.y - mu) * rstd * g4.y + b4.y;
    o.z = (v.z - mu) * rstd * g4.z + b4.z;
    o.w = (v.w - mu) * rstd * g4.w + b4.w;
    *(float4*)&out[(i64)bi * T * H + (i64)t * H + h] = o;
}

__global__ void softmax128_kernel(float* __restrict__ S) {
    float* row = S + (i64)blockIdx.x * 128;
    int tid = threadIdx.x;
    float v = row[tid];
    __shared__ float r1[4], r2[4];
    float m = v;
#pragma unroll
    for (int o = 16; o > 0; o >>= 1) m = fmaxf(m, __shfl_xor_sync(0xffffffffu, m, o));
    if ((tid & 31) == 0) r1[tid >> 5] = m;
    __syncthreads();
    m = fmaxf(fmaxf(r1[0], r1[1]), fmaxf(r1[2], r1[3]));
    float e = __expf(v - m), s = e;
#pragma unroll
    for (int o = 16; o > 0; o >>= 1) s += __shfl_xor_sync(0xffffffffu, s, o);
    if ((tid & 31) == 0) r2[tid >> 5] = s;
    __syncthreads();
    s = r2[0] + r2[1] + r2[2] + r2[3];
    row[tid] = e / s;
}

__global__ void tag_softmax_kernel(const float* __restrict__ logits,
    const int* __restrict__ tag_ids, float* __restrict__ prob,
    float* __restrict__ nll, float* __restrict__ valid)
{
    using namespace cfg;
    int r = blockIdx.x;
    int tid = threadIdx.x;
    const float* lr = logits + (i64)r * NT;
    float v = (tid < NT) ? lr[tid] : -1e30f;
    __shared__ float r1[4], r2[4];
    float m = v;
#pragma unroll
    for (int o = 16; o > 0; o >>= 1) m = fmaxf(m, __shfl_xor_sync(0xffffffffu, m, o));
    if ((tid & 31) == 0) r1[tid >> 5] = m;
    __syncthreads();
    m = fmaxf(fmaxf(r1[0], r1[1]), fmaxf(r1[2], r1[3]));
    float e = (tid < NT) ? __expf(v - m) : 0.f, s = e;
#pragma unroll
    for (int o = 16; o > 0; o >>= 1) s += __shfl_xor_sync(0xffffffffu, s, o);
    if ((tid & 31) == 0) r2[tid >> 5] = s;
    __syncthreads();
    s = r2[0] + r2[1] + r2[2] + r2[3];
    if (tid < NT) prob[(i64)r * NT + tid] = e / s;
    if (tid == 0) {
        int tg = tag_ids[r];
        float n = -(lr[tg] - m - __logf(s));
        float vl = (tg != 0) ? 1.f : 0.f;
        nll[r] = n * vl; valid[r] = vl;
    }
}

__global__ void loss_kernel(const float* __restrict__ nll, const float* __restrict__ valid,
                            float* __restrict__ out) {
    __shared__ float sn[256], sv[256];
    int tid = threadIdx.x;
    float a = 0.f, b = 0.f;
    for (int i = tid; i < cfg::B * cfg::T; i += 256) { a += nll[i]; b += valid[i]; }
    sn[tid] = a; sv[tid] = b;
    __syncthreads();
    for (int st = 128; st > 0; st >>= 1) {
        if (tid < st) { sn[tid] += sn[tid + st]; sv[tid] += sv[tid + st]; }
        __syncthreads();
    }
    if (tid == 0) out[0] = sn[0] / fmaxf(sv[0], 1.f);
}

// ---------------- host orchestration ----------------
extern "C" void kernel_launch(void* const* d_in, const int*, int, void* d_out, int) {
    using namespace cfg;
    const int* ids = (const int*)d_in[0];
    const int* tags = (const int*)d_in[1];
    const float* emb = (const float*)d_in[3];
    const float* eWih = (const float*)d_in[4];
    const float* eWhh = (const float*)d_in[5];
    const float* ebih = (const float*)d_in[6];
    const float* ebhh = (const float*)d_in[7];
    const float* dWih = (const float*)d_in[8];
    const float* dWhh = (const float*)d_in[9];
    const float* dbih = (const float*)d_in[10];
    const float* dbhh = (const float*)d_in[11];
    const float* ln_g = (const float*)d_in[12];
    const float* ln_b = (const float*)d_in[13];
    const float* Wq = (const float*)d_in[14];
    const float* bq = (const float*)d_in[15];
    const float* Wk = (const float*)d_in[16];
    const float* bk = (const float*)d_in[17];
    const float* Wv = (const float*)d_in[18];
    const float* bv = (const float*)d_in[19];
    const float* Wtag = (const float*)d_in[20];
    const float* btag = (const float*)d_in[21];

    float* buf = nullptr;
    cudaGetSymbolAddress((void**)&buf, g_buf);
    uint4* wf = nullptr;            cudaGetSymbolAddress((void**)&wf, g_wf);
    __nv_bfloat16 *xh, *xl, *hh, *hl, *yh, *yl;
    cudaGetSymbolAddress((void**)&xh, g_xh);
    cudaGetSymbolAddress((void**)&xl, g_xl);
    cudaGetSymbolAddress((void**)&hh, g_hh);
    cudaGetSymbolAddress((void**)&hl, g_hl);
    cudaGetSymbolAddress((void**)&yh, g_yh);
    cudaGetSymbolAddress((void**)&yl, g_yl);

    float* y = buf + O_Y;   float* nrm = buf + O_N;
    float* q = buf + O_Q;   float* kx = buf + O_K;  float* vx = buf + O_V;
    float* ao = buf + O_AO; float* sc = buf + O_S;  float* lg = buf + O_LG;
    float* cb = buf + O_CB;
    float* nllp = buf + O_NLL; float* vldp = buf + O_VLD;

    // 5 launches before lstm_mma so it lands in the ncu -s 5 -c 1 window
    wconv_kernel<<<dim3(64, 8, 8), dim3(32, 32)>>>(eWih, eWhh, dWih, dWhh, wf);
    for (int i = 0; i < 4; ++i)
        embed_kernel<<<8192, 128>>>(ids, emb, xh, xl, i * 8192);

    lstm_mma<<<128, 256>>>(y, cb, xh, xl, hh, hl, yh, yl, wf,
                           ebih, ebhh, dbih, dbhh);

    ln_kernel<<<T * B, 128>>>(y, ln_g, ln_b, nrm);

    const int Mq = B * T;
    gemm2_kernel<<<dim3(Mq / 64, 8, 1), 128>>>(nrm, Wq, bq, q, Mq, 512, 512, 512,
                                               1.f, 0, 0, 0, 0);
    gemm2_kernel<<<dim3(Mq / 64, 8, 1), 128>>>(nrm, Wk, bk, kx, Mq, 512, 512, 512,
                                               1.f, 0, 0, 0, 0);
    gemm2_kernel<<<dim3(Mq / 64, 8, 1), 128>>>(nrm, Wv, bv, vx, Mq, 512, 512, 512,
                                               1.f, 0, 0, 0, 0);
    gemm2_kernel<<<dim3(2, 2, B), 128>>>(q, kx, nullptr, sc, 128, 128, 512, 512,
        0.044194173824159216f, 0, (i64)T * H, (i64)T * H, (i64)T * T);
    softmax128_kernel<<<B * T, 128>>>(sc);
    gemm2_kernel<<<dim3(2, 8, B), 128>>>(sc, vx, nullptr, ao, 128, 512, 128, 512,
        1.f, 1, (i64)T * T, (i64)T * H, (i64)T * H);
    gemm2_kernel<<<dim3(Mq / 64, 2, 1), 128>>>(ao, Wtag, btag, lg, Mq, NT, 512, 512,
                                               1.f, 0, 0, 0, 0);
    tag_softmax_kernel<<<B * T, 128>>>(lg, tags, (float*)d_out, nllp, vldp);
    loss_kernel<<<1, 256>>>(nllp, vldp, (float*)d_out + (i64)B * T * NT);
}

// round 14
// speedup vs baseline: 1.9527x; 1.0896x over previous
#include <cuda_runtime.h>
#include <cuda_bf16.h>
#include <math.h>

typedef unsigned long long U64;
typedef unsigned int u32;
typedef long long i64;

namespace cfg {
constexpr int B = 256, T = 128, H = 512, L = 4, NT = 74;
constexpr int BH = B * H;
constexpr i64 BTH = (i64)B * T * H;
constexpr i64 O_Y = 0;
constexpr i64 O_N = O_Y + BTH;
constexpr i64 O_Q = O_N + BTH;
constexpr i64 O_K = O_Q + BTH;
constexpr i64 O_V = O_K + BTH;
constexpr i64 O_AO = O_V + BTH;
constexpr i64 O_S = O_AO + BTH;              // [B,T,T]
constexpr i64 O_LG = O_S + (i64)B * T * T;   // logits
constexpr i64 O_CB = O_LG + (i64)B * T * NT; // c state [L][BH]
constexpr i64 O_NLL = O_CB + (i64)L * BH;
constexpr i64 O_VLD = O_NLL + B * T;
constexpr i64 TOT = O_VLD + B * T;
}
__device__ float g_buf[cfg::TOT];
// W fragments: [sl 8][rank 8][kt 64][q 32][lane 32] x uint4 {bh0,bh1,bl0,bl1}
__device__ uint4 g_wf[8 * 8 * 64 * 32 * 32];
__device__ __nv_bfloat16 g_xh[cfg::BTH], g_xl[cfg::BTH];
__device__ __nv_bfloat16 g_hh[2 * cfg::L * cfg::BH], g_hl[2 * cfg::L * cfg::BH];
__device__ __nv_bfloat16 g_yh[2 * cfg::BH], g_yl[2 * cfg::BH];

__device__ __forceinline__ U64 ffma2(U64 a, U64 b, U64 c) {
    U64 d; asm("fma.rn.f32x2 %0, %1, %2, %3;" : "=l"(d) : "l"(a), "l"(b), "l"(c));
    return d;
}
__device__ __forceinline__ float hsum2(U64 v) {
    float lo, hi; asm("mov.b64 {%0,%1}, %2;" : "=f"(lo), "=f"(hi) : "l"(v));
    return lo + hi;
}
__device__ __forceinline__ float sigf(float x) { return 1.f / (1.f + __expf(-x)); }

__device__ __forceinline__ u32 ldcg32(const __nv_bfloat16* p) {
    u32 v; asm volatile("ld.global.cg.u32 %0, [%1];" : "=r"(v) : "l"(p));
    return v;
}
__device__ __forceinline__ void mma16816(float* d, const u32* a, u32 b0, u32 b1) {
    asm volatile(
        "mma.sync.aligned.m16n8k16.row.col.f32.bf16.bf16.f32 "
        "{%0,%1,%2,%3}, {%4,%5,%6,%7}, {%8,%9}, {%0,%1,%2,%3};"
        : "+f"(d[0]), "+f"(d[1]), "+f"(d[2]), "+f"(d[3])
        : "r"(a[0]), "r"(a[1]), "r"(a[2]), "r"(a[3]), "r"(b0), "r"(b1));
}
__device__ __forceinline__ void cluster_bar() {
    asm volatile("barrier.cluster.arrive.aligned;" ::: "memory");
    asm volatile("barrier.cluster.wait.aligned;" ::: "memory");
}
__device__ __forceinline__ u32 bpack(float a, float b) {
    __nv_bfloat162 t(__float2bfloat16_rn(a), __float2bfloat16_rn(b));
    return *(u32*)&t;
}

// -------- W preconversion (R11-validated layout) ----------
__global__ void wconv_kernel(
    const float* __restrict__ eWih, const float* __restrict__ eWhh,
    const float* __restrict__ dWih, const float* __restrict__ dWhh,
    uint4* __restrict__ wf)
{
    int lane = threadIdx.x, q = threadIdx.y;
    int kt = blockIdx.x, rank = blockIdx.y, sl = blockIdx.z;
    bool enc = sl < 4; int l = sl & 3;
    const float* Wih = (enc ? eWih : dWih) + (i64)l * 2048 * 512;
    const float* Whh = (enc ? eWhh : dWhh) + (i64)l * 2048 * 512;
    int n = (q & 3) * 512 + rank * 64 + (q >> 2) * 8 + (lane >> 2);
    int k0 = kt * 16 + (lane & 3) * 2;
    float v[4];
#pragma unroll
    for (int j = 0; j < 4; ++j) {
        int k = k0 + (j >> 1) * 8 + (j & 1);
        v[j] = (k < 512) ? Wih[(i64)n * 512 + k] : Whh[(i64)n * 512 + k - 512];
    }
    float hi[4], lo[4];
#pragma unroll
    for (int j = 0; j < 4; ++j) {
        __nv_bfloat16 h = __float2bfloat16_rn(v[j]);
        hi[j] = __bfloat162float(h);
        lo[j] = v[j] - hi[j];
    }
    uint4 o;
    o.x = bpack(hi[0], hi[1]); o.y = bpack(hi[2], hi[3]);
    o.z = bpack(lo[0], lo[1]); o.w = bpack(lo[2], lo[3]);
    wf[((((i64)sl * 8 + rank) * 64 + kt) * 32 + q) * 32 + lane] = o;
}

// -------- embedding gather + hi/lo split ----------
__global__ void embed_kernel(const int* __restrict__ ids, const float* __restrict__ emb,
                             __nv_bfloat16* __restrict__ xh, __nv_bfloat16* __restrict__ xl,
                             int base) {
    int bid = base + blockIdx.x;
    if (bid >= cfg::B * cfg::T) return;
    int b = bid >> 7, t = bid & 127;
    i64 id = ids[bid];
    float4 v = ((const float4*)(emb + id * cfg::H))[threadIdx.x];
    i64 o = (i64)t * cfg::BH + (i64)b * cfg::H + threadIdx.x * 4;
    float vv[4] = {v.x, v.y, v.z, v.w};
#pragma unroll
    for (int j = 0; j < 4; ++j) {
        __nv_bfloat16 h = __float2bfloat16_rn(vv[j]);
        xh[o + j] = h;
        xl[o + j] = __float2bfloat16_rn(vv[j] - __bfloat162float(h));
    }
}

// -------- cluster-persistent LSTM on mma.sync, 16 clusters x 8 CTAs ---------
// 128 CTAs x 256 threads (8 warps = 2/SMSP). Cluster = 16 batch rows (M=16);
// rank owns 64 h-cols; warp w owns jl-tile w (8 cols) x 4 gates.
// Both A and W fragments register-prefetched one kt ahead; 3-term accs split.
__global__ void __launch_bounds__(256) __cluster_dims__(8, 1, 1) lstm_mma(
    float* __restrict__ y, float* __restrict__ cbuf,
    const __nv_bfloat16* __restrict__ xh, const __nv_bfloat16* __restrict__ xl,
    __nv_bfloat16* __restrict__ hh, __nv_bfloat16* __restrict__ hl,
    __nv_bfloat16* __restrict__ yh, __nv_bfloat16* __restrict__ yl,
    const uint4* __restrict__ wf,
    const float* __restrict__ ebih, const float* __restrict__ ebhh,
    const float* __restrict__ dbih, const float* __restrict__ dbhh)
{
    using namespace cfg;
    const int tid = threadIdx.x;
    const int lane = tid & 31, w = tid >> 5;
    const int gid = lane >> 2, tig = lane & 3;
    const int rank = blockIdx.x & 7;
    const int r0 = (blockIdx.x >> 3) * 16;

    // zero c and parity-1 h planes (own slice: 16 rows x 64 cols x 4 layers)
    for (int e = tid; e < 4 * 16 * 64; e += 256) {
        int l = e >> 10, row = (e >> 6) & 15, col = e & 63;
        i64 off = (i64)l * BH + (i64)(r0 + row) * H + rank * 64 + col;
        cbuf[off] = 0.f;
        hh[(i64)L * BH + off] = __nv_bfloat16(0.f);
        hl[(i64)L * BH + off] = __nv_bfloat16(0.f);
    }
    __threadfence();
    cluster_bar();

    const i64 rA = (i64)(r0 + gid) * H;

    for (int tt = 0; tt < 2 * T; ++tt) {
        const int p = tt & 1;
        const bool enc = tt < T;
        const float* bih = enc ? ebih : dbih;
        const float* bhh = enc ? ebhh : dbhh;
        for (int l = 0; l < 4; ++l) {
            const __nv_bfloat16 *axh, *axl;
            if (l)            { axh = hh + ((i64)p * L + l - 1) * BH; axl = hl + ((i64)p * L + l - 1) * BH; }
            else if (enc)     { axh = xh + (i64)tt * BH;             axl = xl + (i64)tt * BH; }
            else if (tt == T) { axh = hh + 7LL * BH;                 axl = hl + 7LL * BH; }
            else              { axh = yh + (i64)(1 - p) * BH;        axl = yl + (i64)(1 - p) * BH; }
            const __nv_bfloat16* hph = hh + ((i64)(1 - p) * L + l) * BH;
            const __nv_bfloat16* hpl = hl + ((i64)(1 - p) * L + l) * BH;
            const uint4* wfl = wf + (i64)((enc ? l : 4 + l) * 8 + rank) * 64 * 32 * 32;

            float acc[3][4][4];
#pragma unroll
            for (int s = 0; s < 3; ++s)
#pragma unroll
                for (int g = 0; g < 4; ++g)
#pragma unroll
                    for (int c = 0; c < 4; ++c) acc[s][g][c] = 0.f;

            // prefetched fragments: A [0..3] hi, [4..7] lo; W 4x uint4
            u32 cur[8], nxt[8];
            uint4 Wc[4], Wn[4];
            {
                int k0 = tig * 2;
                cur[0] = ldcg32(axh + rA + k0);     cur[1] = ldcg32(axh + rA + 8 * H + k0);
                cur[2] = ldcg32(axh + rA + k0 + 8); cur[3] = ldcg32(axh + rA + 8 * H + k0 + 8);
                cur[4] = ldcg32(axl + rA + k0);     cur[5] = ldcg32(axl + rA + 8 * H + k0);
                cur[6] = ldcg32(axl + rA + k0 + 8); cur[7] = ldcg32(axl + rA + 8 * H + k0 + 8);
                const uint4* wp = wfl + ((i64)0 * 32 + w * 4) * 32 + lane;
#pragma unroll
                for (int g = 0; g < 4; ++g) Wc[g] = wp[g * 32];
            }
            for (int kt = 0; kt < 64; ++kt) {
                if (kt < 63) {
                    const int kn = kt + 1;
                    const uint4* wpn = wfl + ((i64)kn * 32 + w * 4) * 32 + lane;
#pragma unroll
                    for (int g = 0; g < 4; ++g) Wn[g] = wpn[g * 32];
                    const __nv_bfloat16* sh = (kn < 32) ? axh : hph;
                    const __nv_bfloat16* sl2 = (kn < 32) ? axl : hpl;
                    int k0 = ((kn & 31) * 16) + tig * 2;
                    nxt[0] = ldcg32(sh + rA + k0);      nxt[1] = ldcg32(sh + rA + 8 * H + k0);
                    nxt[2] = ldcg32(sh + rA + k0 + 8);  nxt[3] = ldcg32(sh + rA + 8 * H + k0 + 8);
                    nxt[4] = ldcg32(sl2 + rA + k0);     nxt[5] = ldcg32(sl2 + rA + 8 * H + k0);
                    nxt[6] = ldcg32(sl2 + rA + k0 + 8); nxt[7] = ldcg32(sl2 + rA + 8 * H + k0 + 8);
                }
#pragma unroll
                for (int g = 0; g < 4; ++g) {
                    mma16816(acc[0][g], cur + 0, Wc[g].x, Wc[g].y);   // ah*wh
                    mma16816(acc[1][g], cur + 0, Wc[g].z, Wc[g].w);   // ah*wl
                    mma16816(acc[2][g], cur + 4, Wc[g].x, Wc[g].y);   // al*wh
                }
                if (kt < 63) {
#pragma unroll
                    for (int i = 0; i < 8; ++i) cur[i] = nxt[i];
#pragma unroll
                    for (int g = 0; g < 4; ++g) Wc[g] = Wn[g];
                }
            }

            // epilogue: thread owns 4 outputs (2 rr x 2 cc), col tile = w
            const float* bi = bih + (i64)l * 2048;
            const float* bh2 = bhh + (i64)l * 2048;
            float* yo = (!enc && l == 3) ? (y + (i64)(tt - T) * BH) : nullptr;
            const i64 hbase = ((i64)p * L + l) * BH;
#pragma unroll
            for (int rr = 0; rr < 2; ++rr) {
                const int row = r0 + gid + rr * 8;
#pragma unroll
                for (int cc = 0; cc < 2; ++cc) {
                    const int col = rank * 64 + w * 8 + tig * 2 + cc;
                    const int ci = rr * 2 + cc;
                    float gi = acc[0][0][ci] + acc[1][0][ci] + acc[2][0][ci] + bi[col] + bh2[col];
                    float gf = acc[0][1][ci] + acc[1][1][ci] + acc[2][1][ci] + bi[512 + col] + bh2[512 + col];
                    float gg = acc[0][2][ci] + acc[1][2][ci] + acc[2][2][ci] + bi[1024 + col] + bh2[1024 + col];
                    float go = acc[0][3][ci] + acc[1][3][ci] + acc[2][3][ci] + bi[1536 + col] + bh2[1536 + col];
                    i64 cidx = (i64)l * BH + (i64)row * H + col;
                    float cn = sigf(gf) * cbuf[cidx] + sigf(gi) * tanhf(gg);
                    float hn = sigf(go) * tanhf(cn);
                    cbuf[cidx] = cn;
                    __nv_bfloat16 hb16 = __float2bfloat16_rn(hn);
                    __nv_bfloat16 lb16 = __float2bfloat16_rn(hn - __bfloat162float(hb16));
                    i64 hidx = hbase + (i64)row * H + col;
                    hh[hidx] = hb16;
                    hl[hidx] = lb16;
                    if (yo) {
                        yo[(i64)row * H + col] = hn;
                        yh[(i64)p * BH + (i64)row * H + col] = hb16;
                        yl[(i64)p * BH + (i64)row * H + col] = lb16;
                    }
                }
            }
            __threadfence();
            cluster_bar();
        }
    }
}

// ---------------- generic GEMM (R8-validated) ----------------
__global__ void __launch_bounds__(128) gemm2_kernel(
    const float* __restrict__ A1, const float* __restrict__ W1,
    const float* __restrict__ bias, float* __restrict__ C,
    int M, int N, int K, int ldw, float alpha, int transW,
    i64 sA, i64 sW, i64 sC)
{
    __shared__ float a_s[64 * 34];
    __shared__ float w_s[64 * 34];
    const int tid = threadIdx.x;
    const int ng = tid & 15, mg = tid >> 4;
    const int m0 = blockIdx.x * 64, n0 = blockIdx.y * 64;
    const float* A = A1 + (i64)blockIdx.z * sA;
    const float* W = W1 + (i64)blockIdx.z * sW;
    float* Cb = C + (i64)blockIdx.z * sC;
    U64 acc[8][4];
#pragma unroll
    for (int mm = 0; mm < 8; ++mm)
#pragma unroll
        for (int nn = 0; nn < 4; ++nn) acc[mm][nn] = 0ull;
    for (int kc = 0; kc < K; kc += 32) {
        __syncthreads();
#pragma unroll
        for (int i = 0; i < 4; ++i) {
            int lin = tid + i * 128;
            int row = lin >> 3, c4 = (lin & 7) * 4;
            float4 v = *(const float4*)&A[(i64)(m0 + row) * K + kc + c4];
            float* d = &a_s[row * 34 + c4];
            d[0] = v.x; d[1] = v.y; d[2] = v.z; d[3] = v.w;
        }
        if (!transW) {
#pragma unroll
            for (int i = 0; i < 4; ++i) {
                int lin = tid + i * 128;
                int row = lin >> 3, c4 = (lin & 7) * 4;
                float4 v = make_float4(0.f, 0.f, 0.f, 0.f);
                if (n0 + row < N) v = *(const float4*)&W[(i64)(n0 + row) * ldw + kc + c4];
                float* d = &w_s[row * 34 + c4];
                d[0] = v.x; d[1] = v.y; d[2] = v.z; d[3] = v.w;
            }
        } else {
#pragma unroll
            for (int i = 0; i < 4; ++i) {
                int lin = tid + i * 128;
                int kk = lin >> 4, c4 = (lin & 15) * 4;
                float4 v = *(const float4*)&W[(i64)(kc + kk) * ldw + n0 + c4];
                w_s[(c4 + 0) * 34 + kk] = v.x;
                w_s[(c4 + 1) * 34 + kk] = v.y;
                w_s[(c4 + 2) * 34 + kk] = v.z;
                w_s[(c4 + 3) * 34 + kk] = v.w;
            }
        }
        __syncthreads();
#pragma unroll
        for (int kp = 0; kp < 16; ++kp) {
            U64 wv[4];
#pragma unroll
            for (int nn = 0; nn < 4; ++nn)
                wv[nn] = *(const U64*)&w_s[(ng + nn * 16) * 34 + kp * 2];
#pragma unroll
            for (int mm = 0; mm < 8; ++mm) {
                U64 av = *(const U64*)&a_s[(mg * 8 + mm) * 34 + kp * 2];
#pragma unroll
                for (int nn = 0; nn < 4; ++nn)
                    acc[mm][nn] = ffma2(av, wv[nn], acc[mm][nn]);
            }
        }
    }
#pragma unroll
    for (int mm = 0; mm < 8; ++mm) {
        const int m = m0 + mg * 8 + mm;
#pragma unroll
        for (int nn = 0; nn < 4; ++nn) {
            const int n = n0 + ng + nn * 16;
            if (n < N) {
                float v = hsum2(acc[mm][nn]) * alpha;
                if (bias) v += bias[n];
                Cb[(i64)m * N + n] = v;
            }
        }
    }
}

// ---------------- small kernels ----------------
__global__ void __launch_bounds__(128) ln_kernel(const float* __restrict__ y,
    const float* __restrict__ gam, const float* __restrict__ bet, float* __restrict__ out)
{
    using namespace cfg;
    int r = blockIdx.x;
    int t = r >> 8, bi = r & 255;
    int h = threadIdx.x * 4;
    float4 v = *(const float4*)&y[(i64)r * H + h];
    float s = v.x + v.y + v.z + v.w;
    float sq = v.x * v.x + v.y * v.y + v.z * v.z + v.w * v.w;
#pragma unroll
    for (int o = 16; o > 0; o >>= 1) {
        s += __shfl_xor_sync(0xffffffffu, s, o);
        sq += __shfl_xor_sync(0xffffffffu, sq, o);
    }
    __shared__ float ss[4], sqs[4];
    if ((threadIdx.x & 31) == 0) { ss[threadIdx.x >> 5] = s; sqs[threadIdx.x >> 5] = sq; }
    __syncthreads();
    s = ss[0] + ss[1] + ss[2] + ss[3];
    sq = sqs[0] + sqs[1] + sqs[2] + sqs[3];
    float mu = s * (1.f / 512.f);
    float rstd = rsqrtf(sq * (1.f / 512.f) - mu * mu + 1e-5f);
    float4 g4 = *(const float4*)&gam[h];
    float4 b4 = *(const float4*)&bet[h];
    float4 o;
    o.x = (v.x - mu) * rstd * g4.x + b4.x;
    o.y = (v.y - mu) * rstd * g4.y + b4.y;
    o.z = (v.z - mu) * rstd * g4.z + b4.z;
    o.w = (v.w - mu) * rstd * g4.w + b4.w;
    *(float4*)&out[(i64)bi * T * H + (i64)t * H + h] = o;
}

__global__ void softmax128_kernel(float* __restrict__ S) {
    float* row = S + (i64)blockIdx.x * 128;
    int tid = threadIdx.x;
    float v = row[tid];
    __shared__ float r1[4], r2[4];
    float m = v;
#pragma unroll
    for (int o = 16; o > 0; o >>= 1) m = fmaxf(m, __shfl_xor_sync(0xffffffffu, m, o));
    if ((tid & 31) == 0) r1[tid >> 5] = m;
    __syncthreads();
    m = fmaxf(fmaxf(r1[0], r1[1]), fmaxf(r1[2], r1[3]));
    float e = __expf(v - m), s = e;
#pragma unroll
    for (int o = 16; o > 0; o >>= 1) s += __shfl_xor_sync(0xffffffffu, s, o);
    if ((tid & 31) == 0) r2[tid >> 5] = s;
    __syncthreads();
    s = r2[0] + r2[1] + r2[2] + r2[3];
    row[tid] = e / s;
}

__global__ void tag_softmax_kernel(const float* __restrict__ logits,
    const int* __restrict__ tag_ids, float* __restrict__ prob,
    float* __restrict__ nll, float* __restrict__ valid)
{
    using namespace cfg;
    int r = blockIdx.x;
    int tid = threadIdx.x;
    const float* lr = logits + (i64)r * NT;
    float v = (tid < NT) ? lr[tid] : -1e30f;
    __shared__ float r1[4], r2[4];
    float m = v;
#pragma unroll
    for (int o = 16; o > 0; o >>= 1) m = fmaxf(m, __shfl_xor_sync(0xffffffffu, m, o));
    if ((tid & 31) == 0) r1[tid >> 5] = m;
    __syncthreads();
    m = fmaxf(fmaxf(r1[0], r1[1]), fmaxf(r1[2], r1[3]));
    float e = (tid < NT) ? __expf(v - m) : 0.f, s = e;
#pragma unroll
    for (int o = 16; o > 0; o >>= 1) s += __shfl_xor_sync(0xffffffffu, s, o);
    if ((tid & 31) == 0) r2[tid >> 5] = s;
    __syncthreads();
    s = r2[0] + r2[1] + r2[2] + r2[3];
    if (tid < NT) prob[(i64)r * NT + tid] = e / s;
    if (tid == 0) {
        int tg = tag_ids[r];
        float n = -(lr[tg] - m - __logf(s));
        float vl = (tg != 0) ? 1.f : 0.f;
        nll[r] = n * vl; valid[r] = vl;
    }
}

__global__ void loss_kernel(const float* __restrict__ nll, const float* __restrict__ valid,
                            float* __restrict__ out) {
    __shared__ float sn[256], sv[256];
    int tid = threadIdx.x;
    float a = 0.f, b = 0.f;
    for (int i = tid; i < cfg::B * cfg::T; i += 256) { a += nll[i]; b += valid[i]; }
    sn[tid] = a; sv[tid] = b;
    __syncthreads();
    for (int st = 128; st > 0; st >>= 1) {
        if (tid < st) { sn[tid] += sn[tid + st]; sv[tid] += sv[tid + st]; }
        __syncthreads();
    }
    if (tid == 0) out[0] = sn[0] / fmaxf(sv[0], 1.f);
}

// ---------------- host orchestration ----------------
extern "C" void kernel_launch(void* const* d_in, const int*, int, void* d_out, int) {
    using namespace cfg;
    const int* ids = (const int*)d_in[0];
    const int* tags = (const int*)d_in[1];
    const float* emb = (const float*)d_in[3];
    const float* eWih = (const float*)d_in[4];
    const float* eWhh = (const float*)d_in[5];
    const float* ebih = (const float*)d_in[6];
    const float* ebhh = (const float*)d_in[7];
    const float* dWih = (const float*)d_in[8];
    const float* dWhh = (const float*)d_in[9];
    const float* dbih = (const float*)d_in[10];
    const float* dbhh = (const float*)d_in[11];
    const float* ln_g = (const float*)d_in[12];
    const float* ln_b = (const float*)d_in[13];
    const float* Wq = (const float*)d_in[14];
    const float* bq = (const float*)d_in[15];
    const float* Wk = (const float*)d_in[16];
    const float* bk = (const float*)d_in[17];
    const float* Wv = (const float*)d_in[18];
    const float* bv = (const float*)d_in[19];
    const float* Wtag = (const float*)d_in[20];
    const float* btag = (const float*)d_in[21];

    float* buf = nullptr;
    cudaGetSymbolAddress((void**)&buf, g_buf);
    uint4* wf = nullptr;            cudaGetSymbolAddress((void**)&wf, g_wf);
    __nv_bfloat16 *xh, *xl, *hh, *hl, *yh, *yl;
    cudaGetSymbolAddress((void**)&xh, g_xh);
    cudaGetSymbolAddress((void**)&xl, g_xl);
    cudaGetSymbolAddress((void**)&hh, g_hh);
    cudaGetSymbolAddress((void**)&hl, g_hl);
    cudaGetSymbolAddress((void**)&yh, g_yh);
    cudaGetSymbolAddress((void**)&yl, g_yl);

    float* y = buf + O_Y;   float* nrm = buf + O_N;
    float* q = buf + O_Q;   float* kx = buf + O_K;  float* vx = buf + O_V;
    float* ao = buf + O_AO; float* sc = buf + O_S;  float* lg = buf + O_LG;
    float* cb = buf + O_CB;
    float* nllp = buf + O_NLL; float* vldp = buf + O_VLD;

    // 4 launches before lstm_mma: one hidden harness launch precedes these,
    // so lstm_mma is the 6th recorded launch -> caught by ncu -s 5 -c 1.
    wconv_kernel<<<dim3(64, 8, 8), dim3(32, 32)>>>(eWih, eWhh, dWih, dWhh, wf);
    embed_kernel<<<10923, 128>>>(ids, emb, xh, xl, 0);
    embed_kernel<<<10923, 128>>>(ids, emb, xh, xl, 10923);
    embed_kernel<<<10922, 128>>>(ids, emb, xh, xl, 21846);

    lstm_mma<<<128, 256>>>(y, cb, xh, xl, hh, hl, yh, yl, wf,
                           ebih, ebhh, dbih, dbhh);

    ln_kernel<<<T * B, 128>>>(y, ln_g, ln_b, nrm);

    const int Mq = B * T;
    gemm2_kernel<<<dim3(Mq / 64, 8, 1), 128>>>(nrm, Wq, bq, q, Mq, 512, 512, 512,
                                               1.f, 0, 0, 0, 0);
    gemm2_kernel<<<dim3(Mq / 64, 8, 1), 128>>>(nrm, Wk, bk, kx, Mq, 512, 512, 512,
                                               1.f, 0, 0, 0, 0);
    gemm2_kernel<<<dim3(Mq / 64, 8, 1), 128>>>(nrm, Wv, bv, vx, Mq, 512, 512, 512,
                                               1.f, 0, 0, 0, 0);
    gemm2_kernel<<<dim3(2, 2, B), 128>>>(q, kx, nullptr, sc, 128, 128, 512, 512,
        0.044194173824159216f, 0, (i64)T * H, (i64)T * H, (i64)T * T);
    softmax128_kernel<<<B * T, 128>>>(sc);
    gemm2_kernel<<<dim3(2, 8, B), 128>>>(sc, vx, nullptr, ao, 128, 512, 128, 512,
        1.f, 1, (i64)T * T, (i64)T * H, (i64)T * H);
    gemm2_kernel<<<dim3(Mq / 64, 2, 1), 128>>>(ao, Wtag, btag, lg, Mq, NT, 512, 512,
                                               1.f, 0, 0, 0, 0);
    tag_softmax_kernel<<<B * T, 128>>>(lg, tags, (float*)d_out, nllp, vldp);
    loss_kernel<<<1, 256>>>(nllp, vldp, (float*)d_out + (i64)B * T * NT);
}

// round 15
// speedup vs baseline: 3.5789x; 1.8328x over previous
#include <cuda_runtime.h>
#include <cuda_bf16.h>
#include <math.h>

typedef unsigned long long U64;
typedef unsigned int u32;
typedef long long i64;

namespace cfg {
constexpr int B = 256, T = 128, H = 512, L = 4, NT = 74;
constexpr int BH = B * H;
constexpr i64 BTH = (i64)B * T * H;
constexpr i64 O_Y = 0;
constexpr i64 O_N = O_Y + BTH;
constexpr i64 O_Q = O_N + BTH;
constexpr i64 O_K = O_Q + BTH;
constexpr i64 O_V = O_K + BTH;
constexpr i64 O_AO = O_V + BTH;
constexpr i64 O_S = O_AO + BTH;              // [B,T,T]
constexpr i64 O_LG = O_S + (i64)B * T * T;   // logits
constexpr i64 O_CB = O_LG + (i64)B * T * NT; // c state [L][BH]
constexpr i64 O_NLL = O_CB + (i64)L * BH;
constexpr i64 O_VLD = O_NLL + B * T;
constexpr i64 TOT = O_VLD + B * T;
}
__device__ float g_buf[cfg::TOT];
// W fragments: [sl 8][rank 8][kt 64][q 32][lane 32] x uint4 {bh0,bh1,bl0,bl1}
__device__ uint4 g_wf[8 * 8 * 64 * 32 * 32];
__device__ __nv_bfloat16 g_xh[cfg::BTH], g_xl[cfg::BTH];
__device__ __nv_bfloat16 g_hh[2 * cfg::L * cfg::BH], g_hl[2 * cfg::L * cfg::BH];
__device__ __nv_bfloat16 g_yh[2 * cfg::BH], g_yl[2 * cfg::BH];

__device__ __forceinline__ U64 ffma2(U64 a, U64 b, U64 c) {
    U64 d; asm("fma.rn.f32x2 %0, %1, %2, %3;" : "=l"(d) : "l"(a), "l"(b), "l"(c));
    return d;
}
__device__ __forceinline__ float hsum2(U64 v) {
    float lo, hi; asm("mov.b64 {%0,%1}, %2;" : "=f"(lo), "=f"(hi) : "l"(v));
    return lo + hi;
}
__device__ __forceinline__ float sigf(float x) { return 1.f / (1.f + __expf(-x)); }

__device__ __forceinline__ uint4 ldcg128(const __nv_bfloat16* p) {
    uint4 v;
    asm volatile("ld.global.cg.v4.u32 {%0,%1,%2,%3}, [%4];"
                 : "=r"(v.x), "=r"(v.y), "=r"(v.z), "=r"(v.w) : "l"(p));
    return v;
}
__device__ __forceinline__ void mma16816(float* d, const u32* a, u32 b0, u32 b1) {
    asm volatile(
        "mma.sync.aligned.m16n8k16.row.col.f32.bf16.bf16.f32 "
        "{%0,%1,%2,%3}, {%4,%5,%6,%7}, {%8,%9}, {%0,%1,%2,%3};"
        : "+f"(d[0]), "+f"(d[1]), "+f"(d[2]), "+f"(d[3])
        : "r"(a[0]), "r"(a[1]), "r"(a[2]), "r"(a[3]), "r"(b0), "r"(b1));
}
__device__ __forceinline__ void cluster_bar() {
    asm volatile("barrier.cluster.arrive.aligned;" ::: "memory");
    asm volatile("barrier.cluster.wait.aligned;" ::: "memory");
}
__device__ __forceinline__ u32 bpack(float a, float b) {
    __nv_bfloat162 t(__float2bfloat16_rn(a), __float2bfloat16_rn(b));
    return *(u32*)&t;
}

// -------- W preconversion (R11-validated layout) ----------
__global__ void wconv_kernel(
    const float* __restrict__ eWih, const float* __restrict__ eWhh,
    const float* __restrict__ dWih, const float* __restrict__ dWhh,
    uint4* __restrict__ wf)
{
    int lane = threadIdx.x, q = threadIdx.y;
    int kt = blockIdx.x, rank = blockIdx.y, sl = blockIdx.z;
    bool enc = sl < 4; int l = sl & 3;
    const float* Wih = (enc ? eWih : dWih) + (i64)l * 2048 * 512;
    const float* Whh = (enc ? eWhh : dWhh) + (i64)l * 2048 * 512;
    int n = (q & 3) * 512 + rank * 64 + (q >> 2) * 8 + (lane >> 2);
    int k0 = kt * 16 + (lane & 3) * 2;
    float v[4];
#pragma unroll
    for (int j = 0; j < 4; ++j) {
        int k = k0 + (j >> 1) * 8 + (j & 1);
        v[j] = (k < 512) ? Wih[(i64)n * 512 + k] : Whh[(i64)n * 512 + k - 512];
    }
    float hi[4], lo[4];
#pragma unroll
    for (int j = 0; j < 4; ++j) {
        __nv_bfloat16 h = __float2bfloat16_rn(v[j]);
        hi[j] = __bfloat162float(h);
        lo[j] = v[j] - hi[j];
    }
    uint4 o;
    o.x = bpack(hi[0], hi[1]); o.y = bpack(hi[2], hi[3]);
    o.z = bpack(lo[0], lo[1]); o.w = bpack(lo[2], lo[3]);
    wf[((((i64)sl * 8 + rank) * 64 + kt) * 32 + q) * 32 + lane] = o;
}

// -------- embedding gather + hi/lo split ----------
__global__ void embed_kernel(const int* __restrict__ ids, const float* __restrict__ emb,
                             __nv_bfloat16* __restrict__ xh, __nv_bfloat16* __restrict__ xl,
                             int base) {
    int bid = base + blockIdx.x;
    if (bid >= cfg::B * cfg::T) return;
    int b = bid >> 7, t = bid & 127;
    i64 id = ids[bid];
    float4 v = ((const float4*)(emb + id * cfg::H))[threadIdx.x];
    i64 o = (i64)t * cfg::BH + (i64)b * cfg::H + threadIdx.x * 4;
    float vv[4] = {v.x, v.y, v.z, v.w};
#pragma unroll
    for (int j = 0; j < 4; ++j) {
        __nv_bfloat16 h = __float2bfloat16_rn(vv[j]);
        xh[o + j] = h;
        xl[o + j] = __float2bfloat16_rn(vv[j] - __bfloat162float(h));
    }
}

// -------- cluster-persistent LSTM on mma.sync + smem-staged A ---------------
// 128 CTAs x 256 threads (8 warps = 2/SMSP). Cluster = 16 batch rows (M=16);
// rank owns 64 h-cols; warp w owns jl-tile w (8 cols) x 4 gates.
// A staged in smem once per cell (x||h, hi/lo, pad-4 stride: conflict-free);
// W register-prefetched one kt ahead; 3-term accumulators split.
// smem layout (u32 words): plane p in {hi,lo}: p*8256 + row*516 + kword,
// kword 0..255 = x k 0..511, kword 256..511 = h k 0..511.
__global__ void __launch_bounds__(256) __cluster_dims__(8, 1, 1) lstm_mma(
    float* __restrict__ y, float* __restrict__ cbuf,
    const __nv_bfloat16* __restrict__ xh, const __nv_bfloat16* __restrict__ xl,
    __nv_bfloat16* __restrict__ hh, __nv_bfloat16* __restrict__ hl,
    __nv_bfloat16* __restrict__ yh, __nv_bfloat16* __restrict__ yl,
    const uint4* __restrict__ wf,
    const float* __restrict__ ebih, const float* __restrict__ ebhh,
    const float* __restrict__ dbih, const float* __restrict__ dbhh)
{
    using namespace cfg;
    extern __shared__ u32 As[];        // 16512 words = 66048 B
    const int tid = threadIdx.x;
    const int lane = tid & 31, w = tid >> 5;
    const int gid = lane >> 2, tig = lane & 3;
    const int rank = blockIdx.x & 7;
    const int r0 = (blockIdx.x >> 3) * 16;

    // zero c and parity-1 h planes (own slice: 16 rows x 64 cols x 4 layers)
    for (int e = tid; e < 4 * 16 * 64; e += 256) {
        int l = e >> 10, row = (e >> 6) & 15, col = e & 63;
        i64 off = (i64)l * BH + (i64)(r0 + row) * H + rank * 64 + col;
        cbuf[off] = 0.f;
        hh[(i64)L * BH + off] = __nv_bfloat16(0.f);
        hl[(i64)L * BH + off] = __nv_bfloat16(0.f);
    }
    __threadfence();
    cluster_bar();

    const int abase0 = gid * 516 + tig;          // hi plane, row gid
    const int abase1 = (gid + 8) * 516 + tig;    // hi plane, row gid+8

    for (int tt = 0; tt < 2 * T; ++tt) {
        const int p = tt & 1;
        const bool enc = tt < T;
        const float* bih = enc ? ebih : dbih;
        const float* bhh = enc ? ebhh : dbhh;
        for (int l = 0; l < 4; ++l) {
            const __nv_bfloat16 *axh, *axl;
            if (l)            { axh = hh + ((i64)p * L + l - 1) * BH; axl = hl + ((i64)p * L + l - 1) * BH; }
            else if (enc)     { axh = xh + (i64)tt * BH;             axl = xl + (i64)tt * BH; }
            else if (tt == T) { axh = hh + 7LL * BH;                 axl = hl + 7LL * BH; }
            else              { axh = yh + (i64)(1 - p) * BH;        axl = yl + (i64)(1 - p) * BH; }
            const __nv_bfloat16* hph = hh + ((i64)(1 - p) * L + l) * BH;
            const __nv_bfloat16* hpl = hl + ((i64)(1 - p) * L + l) * BH;
            const uint4* wfl = wf + (i64)((enc ? l : 4 + l) * 8 + rank) * 64 * 32 * 32;

            // ---- stage A: 4096 uint4 (2 src x 2 plane x 16 rows x 64 u4) ----
#pragma unroll
            for (int i = 0; i < 16; ++i) {
                int idx = tid + i * 256;
                int src = idx >> 11;               // 0 = x-part, 1 = h-part
                int rem = idx & 2047;
                int plane = rem >> 10;
                int row = (rem >> 4) & 15;
                int u = rem & 15;                  // 16 u4 per (row,src) quarter? -> 64 u4/row: recompute
                // re-derive: per (src,plane): 16 rows x 64 u4 = 1024
                int rem2 = rem & 1023;
                row = rem2 >> 6;
                u = rem2 & 63;
                const __nv_bfloat16* sp =
                    src ? (plane ? hpl : hph) : (plane ? axl : axh);
                uint4 v = ldcg128(sp + (i64)(r0 + row) * H + u * 8);
                // smem word addr: plane*8256 + row*516 + src*256 + u*4
                *(uint4*)&As[plane * 8256 + row * 516 + src * 256 + u * 4] = v;
            }
            __syncthreads();

            float acc[3][4][4];
#pragma unroll
            for (int s = 0; s < 3; ++s)
#pragma unroll
                for (int g = 0; g < 4; ++g)
#pragma unroll
                    for (int c = 0; c < 4; ++c) acc[s][g][c] = 0.f;

            uint4 Wc[4], Wn[4];
            {
                const uint4* wp = wfl + ((i64)0 * 32 + w * 4) * 32 + lane;
#pragma unroll
                for (int g = 0; g < 4; ++g) Wc[g] = wp[g * 32];
            }
            for (int kt = 0; kt < 64; ++kt) {
                if (kt < 63) {
                    const uint4* wpn = wfl + ((i64)(kt + 1) * 32 + w * 4) * 32 + lane;
#pragma unroll
                    for (int g = 0; g < 4; ++g) Wn[g] = wpn[g * 32];
                }
                const int kw = kt * 8;
                u32 a[8];
                a[0] = As[abase0 + kw];            a[1] = As[abase1 + kw];
                a[2] = As[abase0 + kw + 4];        a[3] = As[abase1 + kw + 4];
                a[4] = As[8256 + abase0 + kw];     a[5] = As[8256 + abase1 + kw];
                a[6] = As[8256 + abase0 + kw + 4]; a[7] = As[8256 + abase1 + kw + 4];
#pragma unroll
                for (int g = 0; g < 4; ++g) {
                    mma16816(acc[0][g], a + 0, Wc[g].x, Wc[g].y);   // ah*wh
                    mma16816(acc[1][g], a + 0, Wc[g].z, Wc[g].w);   // ah*wl
                    mma16816(acc[2][g], a + 4, Wc[g].x, Wc[g].y);   // al*wh
                }
                if (kt < 63) {
#pragma unroll
                    for (int g = 0; g < 4; ++g) Wc[g] = Wn[g];
                }
            }

            // epilogue: thread owns 4 outputs (2 rr x 2 cc), col tile = w
            const float* bi = bih + (i64)l * 2048;
            const float* bh2 = bhh + (i64)l * 2048;
            float* yo = (!enc && l == 3) ? (y + (i64)(tt - T) * BH) : nullptr;
            const i64 hbase = ((i64)p * L + l) * BH;
#pragma unroll
            for (int rr = 0; rr < 2; ++rr) {
                const int row = r0 + gid + rr * 8;
#pragma unroll
                for (int cc = 0; cc < 2; ++cc) {
                    const int col = rank * 64 + w * 8 + tig * 2 + cc;
                    const int ci = rr * 2 + cc;
                    float gi = acc[0][0][ci] + acc[1][0][ci] + acc[2][0][ci] + bi[col] + bh2[col];
                    float gf = acc[0][1][ci] + acc[1][1][ci] + acc[2][1][ci] + bi[512 + col] + bh2[512 + col];
                    float gg = acc[0][2][ci] + acc[1][2][ci] + acc[2][2][ci] + bi[1024 + col] + bh2[1024 + col];
                    float go = acc[0][3][ci] + acc[1][3][ci] + acc[2][3][ci] + bi[1536 + col] + bh2[1536 + col];
                    i64 cidx = (i64)l * BH + (i64)row * H + col;
                    float cn = sigf(gf) * cbuf[cidx] + sigf(gi) * tanhf(gg);
                    float hn = sigf(go) * tanhf(cn);
                    cbuf[cidx] = cn;
                    __nv_bfloat16 hb16 = __float2bfloat16_rn(hn);
                    __nv_bfloat16 lb16 = __float2bfloat16_rn(hn - __bfloat162float(hb16));
                    i64 hidx = hbase + (i64)row * H + col;
                    hh[hidx] = hb16;
                    hl[hidx] = lb16;
                    if (yo) {
                        yo[(i64)row * H + col] = hn;
                        yh[(i64)p * BH + (i64)row * H + col] = hb16;
                        yl[(i64)p * BH + (i64)row * H + col] = lb16;
                    }
                }
            }
            __threadfence();
            cluster_bar();
        }
    }
}

// ---------------- generic GEMM (R8-validated) ----------------
__global__ void __launch_bounds__(128) gemm2_kernel(
    const float* __restrict__ A1, const float* __restrict__ W1,
    const float* __restrict__ bias, float* __restrict__ C,
    int M, int N, int K, int ldw, float alpha, int transW,
    i64 sA, i64 sW, i64 sC)
{
    __shared__ float a_s[64 * 34];
    __shared__ float w_s[64 * 34];
    const int tid = threadIdx.x;
    const int ng = tid & 15, mg = tid >> 4;
    const int m0 = blockIdx.x * 64, n0 = blockIdx.y * 64;
    const float* A = A1 + (i64)blockIdx.z * sA;
    const float* W = W1 + (i64)blockIdx.z * sW;
    float* Cb = C + (i64)blockIdx.z * sC;
    U64 acc[8][4];
#pragma unroll
    for (int mm = 0; mm < 8; ++mm)
#pragma unroll
        for (int nn = 0; nn < 4; ++nn) acc[mm][nn] = 0ull;
    for (int kc = 0; kc < K; kc += 32) {
        __syncthreads();
#pragma unroll
        for (int i = 0; i < 4; ++i) {
            int lin = tid + i * 128;
            int row = lin >> 3, c4 = (lin & 7) * 4;
            float4 v = *(const float4*)&A[(i64)(m0 + row) * K + kc + c4];
            float* d = &a_s[row * 34 + c4];
            d[0] = v.x; d[1] = v.y; d[2] = v.z; d[3] = v.w;
        }
        if (!transW) {
#pragma unroll
            for (int i = 0; i < 4; ++i) {
                int lin = tid + i * 128;
                int row = lin >> 3, c4 = (lin & 7) * 4;
                float4 v = make_float4(0.f, 0.f, 0.f, 0.f);
                if (n0 + row < N) v = *(const float4*)&W[(i64)(n0 + row) * ldw + kc + c4];
                float* d = &w_s[row * 34 + c4];
                d[0] = v.x; d[1] = v.y; d[2] = v.z; d[3] = v.w;
            }
        } else {
#pragma unroll
            for (int i = 0; i < 4; ++i) {
                int lin = tid + i * 128;
                int kk = lin >> 4, c4 = (lin & 15) * 4;
                float4 v = *(const float4*)&W[(i64)(kc + kk) * ldw + n0 + c4];
                w_s[(c4 + 0) * 34 + kk] = v.x;
                w_s[(c4 + 1) * 34 + kk] = v.y;
                w_s[(c4 + 2) * 34 + kk] = v.z;
                w_s[(c4 + 3) * 34 + kk] = v.w;
            }
        }
        __syncthreads();
#pragma unroll
        for (int kp = 0; kp < 16; ++kp) {
            U64 wv[4];
#pragma unroll
            for (int nn = 0; nn < 4; ++nn)
                wv[nn] = *(const U64*)&w_s[(ng + nn * 16) * 34 + kp * 2];
#pragma unroll
            for (int mm = 0; mm < 8; ++mm) {
                U64 av = *(const U64*)&a_s[(mg * 8 + mm) * 34 + kp * 2];
#pragma unroll
                for (int nn = 0; nn < 4; ++nn)
                    acc[mm][nn] = ffma2(av, wv[nn], acc[mm][nn]);
            }
        }
    }
#pragma unroll
    for (int mm = 0; mm < 8; ++mm) {
        const int m = m0 + mg * 8 + mm;
#pragma unroll
        for (int nn = 0; nn < 4; ++nn) {
            const int n = n0 + ng + nn * 16;
            if (n < N) {
                float v = hsum2(acc[mm][nn]) * alpha;
                if (bias) v += bias[n];
                Cb[(i64)m * N + n] = v;
            }
        }
    }
}

// ---------------- small kernels ----------------
__global__ void __launch_bounds__(128) ln_kernel(const float* __restrict__ y,
    const float* __restrict__ gam, const float* __restrict__ bet, float* __restrict__ out)
{
    using namespace cfg;
    int r = blockIdx.x;
    int t = r >> 8, bi = r & 255;
    int h = threadIdx.x * 4;
    float4 v = *(const float4*)&y[(i64)r * H + h];
    float s = v.x + v.y + v.z + v.w;
    float sq = v.x * v.x + v.y * v.y + v.z * v.z + v.w * v.w;
#pragma unroll
    for (int o = 16; o > 0; o >>= 1) {
        s += __shfl_xor_sync(0xffffffffu, s, o);
        sq += __shfl_xor_sync(0xffffffffu, sq, o);
    }
    __shared__ float ss[4], sqs[4];
    if ((threadIdx.x & 31) == 0) { ss[threadIdx.x >> 5] = s; sqs[threadIdx.x >> 5] = sq; }
    __syncthreads();
    s = ss[0] + ss[1] + ss[2] + ss[3];
    sq = sqs[0] + sqs[1] + sqs[2] + sqs[3];
    float mu = s * (1.f / 512.f);
    float rstd = rsqrtf(sq * (1.f / 512.f) - mu * mu + 1e-5f);
    float4 g4 = *(const float4*)&gam[h];
    float4 b4 = *(const float4*)&bet[h];
    float4 o;
    o.x = (v.x - mu) * rstd * g4.x + b4.x;
    o.y = (v.y - mu) * rstd * g4.y + b4.y;
    o.z = (v.z - mu) * rstd * g4.z + b4.z;
    o.w = (v.w - mu) * rstd * g4.w + b4.w;
    *(float4*)&out[(i64)bi * T * H + (i64)t * H + h] = o;
}

__global__ void softmax128_kernel(float* __restrict__ S) {
    float* row = S + (i64)blockIdx.x * 128;
    int tid = threadIdx.x;
    float v = row[tid];
    __shared__ float r1[4], r2[4];
    float m = v;
#pragma unroll
    for (int o = 16; o > 0; o >>= 1) m = fmaxf(m, __shfl_xor_sync(0xffffffffu, m, o));
    if ((tid & 31) == 0) r1[tid >> 5] = m;
    __syncthreads();
    m = fmaxf(fmaxf(r1[0], r1[1]), fmaxf(r1[2], r1[3]));
    float e = __expf(v - m), s = e;
#pragma unroll
    for (int o = 16; o > 0; o >>= 1) s += __shfl_xor_sync(0xffffffffu, s, o);
    if ((tid & 31) == 0) r2[tid >> 5] = s;
    __syncthreads();
    s = r2[0] + r2[1] + r2[2] + r2[3];
    row[tid] = e / s;
}

__global__ void tag_softmax_kernel(const float* __restrict__ logits,
    const int* __restrict__ tag_ids, float* __restrict__ prob,
    float* __restrict__ nll, float* __restrict__ valid)
{
    using namespace cfg;
    int r = blockIdx.x;
    int tid = threadIdx.x;
    const float* lr = logits + (i64)r * NT;
    float v = (tid < NT) ? lr[tid] : -1e30f;
    __shared__ float r1[4], r2[4];
    float m = v;
#pragma unroll
    for (int o = 16; o > 0; o >>= 1) m = fmaxf(m, __shfl_xor_sync(0xffffffffu, m, o));
    if ((tid & 31) == 0) r1[tid >> 5] = m;
    __syncthreads();
    m = fmaxf(fmaxf(r1[0], r1[1]), fmaxf(r1[2], r1[3]));
    float e = (tid < NT) ? __expf(v - m) : 0.f, s = e;
#pragma unroll
    for (int o = 16; o > 0; o >>= 1) s += __shfl_xor_sync(0xffffffffu, s, o);
    if ((tid & 31) == 0) r2[tid >> 5] = s;
    __syncthreads();
    s = r2[0] + r2[1] + r2[2] + r2[3];
    if (tid < NT) prob[(i64)r * NT + tid] = e / s;
    if (tid == 0) {
        int tg = tag_ids[r];
        float n = -(lr[tg] - m - __logf(s));
        float vl = (tg != 0) ? 1.f : 0.f;
        nll[r] = n * vl; valid[r] = vl;
    }
}

__global__ void loss_kernel(const float* __restrict__ nll, const float* __restrict__ valid,
                            float* __restrict__ out) {
    __shared__ float sn[256], sv[256];
    int tid = threadIdx.x;
    float a = 0.f, b = 0.f;
    for (int i = tid; i < cfg::B * cfg::T; i += 256) { a += nll[i]; b += valid[i]; }
    sn[tid] = a; sv[tid] = b;
    __syncthreads();
    for (int st = 128; st > 0; st >>= 1) {
        if (tid < st) { sn[tid] += sn[tid + st]; sv[tid] += sv[tid + st]; }
        __syncthreads();
    }
    if (tid == 0) out[0] = sn[0] / fmaxf(sv[0], 1.f);
}

// ---------------- host orchestration ----------------
extern "C" void kernel_launch(void* const* d_in, const int*, int, void* d_out, int) {
    using namespace cfg;
    const int* ids = (const int*)d_in[0];
    const int* tags = (const int*)d_in[1];
    const float* emb = (const float*)d_in[3];
    const float* eWih = (const float*)d_in[4];
    const float* eWhh = (const float*)d_in[5];
    const float* ebih = (const float*)d_in[6];
    const float* ebhh = (const float*)d_in[7];
    const float* dWih = (const float*)d_in[8];
    const float* dWhh = (const float*)d_in[9];
    const float* dbih = (const float*)d_in[10];
    const float* dbhh = (const float*)d_in[11];
    const float* ln_g = (const float*)d_in[12];
    const float* ln_b = (const float*)d_in[13];
    const float* Wq = (const float*)d_in[14];
    const float* bq = (const float*)d_in[15];
    const float* Wk = (const float*)d_in[16];
    const float* bk = (const float*)d_in[17];
    const float* Wv = (const float*)d_in[18];
    const float* bv = (const float*)d_in[19];
    const float* Wtag = (const float*)d_in[20];
    const float* btag = (const float*)d_in[21];

    float* buf = nullptr;
    cudaGetSymbolAddress((void**)&buf, g_buf);
    uint4* wf = nullptr;            cudaGetSymbolAddress((void**)&wf, g_wf);
    __nv_bfloat16 *xh, *xl, *hh, *hl, *yh, *yl;
    cudaGetSymbolAddress((void**)&xh, g_xh);
    cudaGetSymbolAddress((void**)&xl, g_xl);
    cudaGetSymbolAddress((void**)&hh, g_hh);
    cudaGetSymbolAddress((void**)&hl, g_hl);
    cudaGetSymbolAddress((void**)&yh, g_yh);
    cudaGetSymbolAddress((void**)&yl, g_yl);

    float* y = buf + O_Y;   float* nrm = buf + O_N;
    float* q = buf + O_Q;   float* kx = buf + O_K;  float* vx = buf + O_V;
    float* ao = buf + O_AO; float* sc = buf + O_S;  float* lg = buf + O_LG;
    float* cb = buf + O_CB;
    float* nllp = buf + O_NLL; float* vldp = buf + O_VLD;

    const int SMEMSZ = 66048;
    static bool attr_set = false;
    if (!attr_set) {
        cudaFuncSetAttribute(lstm_mma, cudaFuncAttributeMaxDynamicSharedMemorySize, SMEMSZ);
        attr_set = true;
    }

    // 4 launches before lstm_mma (one hidden harness launch precedes them):
    // lstm_mma is the 6th recorded launch -> caught by ncu -s 5 -c 1.
    wconv_kernel<<<dim3(64, 8, 8), dim3(32, 32)>>>(eWih, eWhh, dWih, dWhh, wf);
    embed_kernel<<<10923, 128>>>(ids, emb, xh, xl, 0);
    embed_kernel<<<10923, 128>>>(ids, emb, xh, xl, 10923);
    embed_kernel<<<10922, 128>>>(ids, emb, xh, xl, 21846);

    lstm_mma<<<128, 256, SMEMSZ>>>(y, cb, xh, xl, hh, hl, yh, yl, wf,
                                   ebih, ebhh, dbih, dbhh);

    ln_kernel<<<T * B, 128>>>(y, ln_g, ln_b, nrm);

    const int Mq = B * T;
    gemm2_kernel<<<dim3(Mq / 64, 8, 1), 128>>>(nrm, Wq, bq, q, Mq, 512, 512, 512,
                                               1.f, 0, 0, 0, 0);
    gemm2_kernel<<<dim3(Mq / 64, 8, 1), 128>>>(nrm, Wk, bk, kx, Mq, 512, 512, 512,
                                               1.f, 0, 0, 0, 0);
    gemm2_kernel<<<dim3(Mq / 64, 8, 1), 128>>>(nrm, Wv, bv, vx, Mq, 512, 512, 512,
                                               1.f, 0, 0, 0, 0);
    gemm2_kernel<<<dim3(2, 2, B), 128>>>(q, kx, nullptr, sc, 128, 128, 512, 512,
        0.044194173824159216f, 0, (i64)T * H, (i64)T * H, (i64)T * T);
    softmax128_kernel<<<B * T, 128>>>(sc);
    gemm2_kernel<<<dim3(2, 8, B), 128>>>(sc, vx, nullptr, ao, 128, 512, 128, 512,
        1.f, 1, (i64)T * T, (i64)T * H, (i64)T * H);
    gemm2_kernel<<<dim3(Mq / 64, 2, 1), 128>>>(ao, Wtag, btag, lg, Mq, NT, 512, 512,
                                               1.f, 0, 0, 0, 0);
    tag_softmax_kernel<<<B * T, 128>>>(lg, tags, (float*)d_out, nllp, vldp);
    loss_kernel<<<1, 256>>>(nllp, vldp, (float*)d_out + (i64)B * T * NT);
}